// round 1
// baseline (speedup 1.0000x reference)
#include <cuda_runtime.h>
#include <math.h>

// ---------------- problem constants ----------------
#define CAMS   4
#define DSLICE 4      // D = NDISP/2
#define NDISP  8
#define IH     640
#define IW     1280
#define FH     320
#define FW     640
#define C1     32
#define HO     256
#define WO     256
#define CF     128    // fused cost channels
#define C2     64
#define C3     32

// ---------------- scratch (static device memory; no allocs) ----------------
__device__ float g_feat [(size_t)CAMS*FH*FW*C1];            // [cam][y][x][c]      104.9 MB
__device__ float g_warp [(size_t)CAMS*DSLICE*FH*FW*C1];     // [cam][d][y][x][c]   419.4 MB
__device__ float g_costs[(size_t)DSLICE*HO*WO*CF];          // [d][h][w][c128]     134.2 MB
__device__ float g_x1   [(size_t)DSLICE*HO*WO*C2];          // [d][h][w][c]
__device__ float g_x2   [(size_t)DSLICE*HO*WO*C3];
__device__ float g_x3   [(size_t)DSLICE*HO*WO];
__device__ float g_wf_t [C2*CF*27];                         // transposed fusion weights
__device__ float g_wr1_t[C3*C2*27];                         // transposed reg1 weights

// ---------------- K0: weight transpose OIDHW -> [kdkh][ic][kw][oc] ----------------
__global__ void k_wtrans(const float* __restrict__ w, int which, int COUTn, int CINn)
{
    int n = COUTn * CINn * 27;
    int i = blockIdx.x * 256 + threadIdx.x;
    if (i >= n) return;
    int oc = i % COUTn;
    int r  = i / COUTn;
    int kw = r % 3;  r /= 3;
    int ic = r % CINn;
    int kdkh = r / CINn;
    float v = w[((size_t)oc * CINn + ic) * 27 + kdkh * 3 + kw];
    if (which == 0) g_wf_t[i]  = v;
    else            g_wr1_t[i] = v;
}

// ---------------- K1: conv2d stride2 3->32 + relu, channels-last output ----------------
__global__ void k_feat(const float* __restrict__ cam, const float* __restrict__ w, int cam_idx)
{
    __shared__ float ws[27 * 32];                 // [k][oc]
    int tid = threadIdx.y * 16 + threadIdx.x;
    for (int i = tid; i < 864; i += 256) {
        int k = i >> 5, oc = i & 31;
        ws[i] = w[oc * 27 + k];
    }
    __syncthreads();

    int ow = blockIdx.x * 16 + threadIdx.x;
    int oh = blockIdx.y * 16 + threadIdx.y;

    float v[27];
#pragma unroll
    for (int ic = 0; ic < 3; ic++)
#pragma unroll
        for (int kh = 0; kh < 3; kh++)
#pragma unroll
            for (int kw = 0; kw < 3; kw++) {
                int iy = 2 * oh + kh - 1;
                int ix = 2 * ow + kw - 1;
                float t = 0.f;
                if (iy >= 0 && iy < IH && ix >= 0 && ix < IW)
                    t = cam[(size_t)ic * IH * IW + (size_t)iy * IW + ix];
                v[ic * 9 + kh * 3 + kw] = t;
            }

    float4 acc[8];
#pragma unroll
    for (int q = 0; q < 8; q++) acc[q] = make_float4(0.f, 0.f, 0.f, 0.f);
    const float4* ws4 = (const float4*)ws;
#pragma unroll
    for (int k = 0; k < 27; k++) {
        float vv = v[k];
#pragma unroll
        for (int q = 0; q < 8; q++) {
            float4 wv = ws4[k * 8 + q];
            acc[q].x += vv * wv.x;  acc[q].y += vv * wv.y;
            acc[q].z += vv * wv.z;  acc[q].w += vv * wv.w;
        }
    }
    float4* o = (float4*)(g_feat + ((size_t)cam_idx * FH * FW + (size_t)oh * FW + ow) * C1);
#pragma unroll
    for (int q = 0; q < 8; q++) {
        float4 r = acc[q];
        r.x = fmaxf(r.x, 0.f); r.y = fmaxf(r.y, 0.f);
        r.z = fmaxf(r.z, 0.f); r.w = fmaxf(r.w, 0.f);
        o[q] = r;
    }
}

// ---------------- K2: grid_sample (align_corners=False, zero pad) ----------------
__global__ void k_warp(const float* __restrict__ grids)
{
    int tid = threadIdx.x;
    int pos = blockIdx.x * 256 + tid;      // 0 .. FH*FW
    int d   = blockIdx.y;
    int cam = blockIdx.z;
    int y = pos / FW, x = pos % FW;

    const float* g = grids + ((((size_t)cam * DSLICE + d) * FH + y) * FW + x) * 2;
    float fx = (g[0] + 1.f) * (FW * 0.5f) - 0.5f;
    float fy = (g[1] + 1.f) * (FH * 0.5f) - 0.5f;
    float x0f = floorf(fx), y0f = floorf(fy);
    float wx = fx - x0f,   wy = fy - y0f;
    int x0 = (int)x0f, y0 = (int)y0f;
    int x1 = x0 + 1,   y1 = y0 + 1;
    float vx0 = (x0 >= 0 && x0 < FW) ? 1.f : 0.f;
    float vx1 = (x1 >= 0 && x1 < FW) ? 1.f : 0.f;
    float vy0 = (y0 >= 0 && y0 < FH) ? 1.f : 0.f;
    float vy1 = (y1 >= 0 && y1 < FH) ? 1.f : 0.f;
    float w00 = (1.f - wx) * (1.f - wy) * vx0 * vy0;
    float w01 = wx * (1.f - wy) * vx1 * vy0;
    float w10 = (1.f - wx) * wy * vx0 * vy1;
    float w11 = wx * wy * vx1 * vy1;
    int x0c = min(max(x0, 0), FW - 1), x1c = min(max(x1, 0), FW - 1);
    int y0c = min(max(y0, 0), FH - 1), y1c = min(max(y1, 0), FH - 1);

    const float* fb = g_feat + (size_t)cam * FH * FW * C1;
    const float4* f00 = (const float4*)(fb + ((size_t)y0c * FW + x0c) * C1);
    const float4* f01 = (const float4*)(fb + ((size_t)y0c * FW + x1c) * C1);
    const float4* f10 = (const float4*)(fb + ((size_t)y1c * FW + x0c) * C1);
    const float4* f11 = (const float4*)(fb + ((size_t)y1c * FW + x1c) * C1);
    float4* o = (float4*)(g_warp + ((((size_t)cam * DSLICE + d) * FH + y) * FW + x) * C1);
#pragma unroll
    for (int q = 0; q < 8; q++) {
        float4 a = f00[q], b = f01[q], c = f10[q], e = f11[q];
        float4 r;
        r.x = w00 * a.x + w01 * b.x + w10 * c.x + w11 * e.x;
        r.y = w00 * a.y + w01 * b.y + w10 * c.y + w11 * e.y;
        r.z = w00 * a.z + w01 * b.z + w10 * c.z + w11 * e.z;
        r.w = w00 * a.w + w01 * b.w + w10 * c.w + w11 * e.w;
        o[q] = r;
    }
}

// ---------------- K3: jax.image.resize bilinear (antialias=True) 320x640 -> 256x256 ----------------
__global__ void k_resize()
{
    int wo  = threadIdx.x;
    int ho  = blockIdx.x;
    int d   = blockIdx.y;
    int cam = blockIdx.z;

    // H axis: in=320 out=256, inv_scale=1.25, kernel_scale=1.25
    float sy = (ho + 0.5f) * 1.25f - 0.5f;
    int jy0 = max((int)ceilf(sy - 1.25f), 0);
    int jy1 = min((int)floorf(sy + 1.25f), FH - 1);
    float wyv[4]; int ny = jy1 - jy0 + 1;
    float sumy = 0.f;
    for (int i = 0; i < ny; i++) {
        float w = fmaxf(1.f - fabsf(sy - (float)(jy0 + i)) * 0.8f, 0.f);
        wyv[i] = w; sumy += w;
    }
    for (int i = 0; i < ny; i++) wyv[i] /= sumy;

    // W axis: in=640 out=256, inv_scale=2.5, kernel_scale=2.5
    float sx = (wo + 0.5f) * 2.5f - 0.5f;
    int jx0 = max((int)ceilf(sx - 2.5f), 0);
    int jx1 = min((int)floorf(sx + 2.5f), FW - 1);
    float wxv[6]; int nx = jx1 - jx0 + 1;
    float sumx = 0.f;
    for (int i = 0; i < nx; i++) {
        float w = fmaxf(1.f - fabsf(sx - (float)(jx0 + i)) * 0.4f, 0.f);
        wxv[i] = w; sumx += w;
    }
    for (int i = 0; i < nx; i++) wxv[i] /= sumx;

    float4 acc[8];
#pragma unroll
    for (int q = 0; q < 8; q++) acc[q] = make_float4(0.f, 0.f, 0.f, 0.f);

    const float* base = g_warp + ((size_t)cam * DSLICE + d) * (size_t)FH * FW * C1;
    for (int iy = 0; iy < ny; iy++) {
        const float* rowb = base + (size_t)(jy0 + iy) * FW * C1;
        for (int ix = 0; ix < nx; ix++) {
            float wgt = wyv[iy] * wxv[ix];
            const float4* p = (const float4*)(rowb + (size_t)(jx0 + ix) * C1);
#pragma unroll
            for (int q = 0; q < 8; q++) {
                float4 t = p[q];
                acc[q].x += wgt * t.x; acc[q].y += wgt * t.y;
                acc[q].z += wgt * t.z; acc[q].w += wgt * t.w;
            }
        }
    }
    float4* o = (float4*)(g_costs + (((size_t)d * HO + ho) * WO + wo) * CF + cam * C1);
#pragma unroll
    for (int q = 0; q < 8; q++) o[q] = acc[q];
}

// ---------------- K4: conv3d 3x3x3 pad1 + optional relu (channels-last, implicit GEMM) --------------
// Block: 128 positions (1 row) x COUT oc.  Thread: 4 pos (strided by 32) x 8 oc.
template<int CIN, int COUT>
__global__ void __launch_bounds__(32 * (COUT / 8))
k_conv3d(const float* __restrict__ in, const float* __restrict__ wt,
         float* __restrict__ out, int do_relu)
{
    __shared__ float in_s[32][131];            // [ic][pos 0..129] -> ow0-1+p, stride 131: bank-clean
    __shared__ float w_s[32 * 3 * COUT];       // [ic][kw][oc]
    const int NT  = 32 * (COUT / 8);
    int tid = threadIdx.x;
    int pg  = tid & 31;
    int og  = tid >> 5;
    int ow0 = blockIdx.x * 128;
    int oh  = blockIdx.y;
    int od  = blockIdx.z;

    float acc[4][8];
#pragma unroll
    for (int j = 0; j < 4; j++)
#pragma unroll
        for (int q = 0; q < 8; q++) acc[j][q] = 0.f;

    for (int kd = 0; kd < 3; kd++) {
        int zd = od + kd - 1;
        if (zd < 0 || zd >= DSLICE) continue;
        for (int kh = 0; kh < 3; kh++) {
            int zh = oh + kh - 1;
            if (zh < 0 || zh >= HO) continue;
            const float* inrow = in + ((size_t)zd * HO + zh) * WO * CIN;
            for (int icc = 0; icc < CIN / 32; icc++) {
                __syncthreads();
                // stage input row slice (transposed to ic-major)
                for (int idx = tid; idx < 130 * 32; idx += NT) {
                    int p = idx >> 5, c = idx & 31;
                    int w = ow0 - 1 + p;
                    in_s[c][p] = (w >= 0 && w < WO) ? inrow[(size_t)w * CIN + icc * 32 + c] : 0.f;
                }
                // stage weights (contiguous copy thanks to k_wtrans layout)
                const float* wsrc = wt + ((size_t)((kd * 3 + kh) * CIN + icc * 32)) * 3 * COUT;
                for (int idx = tid; idx < 32 * 3 * COUT; idx += NT) w_s[idx] = wsrc[idx];
                __syncthreads();

#pragma unroll 2
                for (int c = 0; c < 32; c++) {
                    float wreg[3][8];
#pragma unroll
                    for (int kw = 0; kw < 3; kw++) {
                        float4 a = *(const float4*)&w_s[(c * 3 + kw) * COUT + og * 8];
                        float4 b = *(const float4*)&w_s[(c * 3 + kw) * COUT + og * 8 + 4];
                        wreg[kw][0] = a.x; wreg[kw][1] = a.y; wreg[kw][2] = a.z; wreg[kw][3] = a.w;
                        wreg[kw][4] = b.x; wreg[kw][5] = b.y; wreg[kw][6] = b.z; wreg[kw][7] = b.w;
                    }
#pragma unroll
                    for (int j = 0; j < 4; j++) {
                        int p = pg + 32 * j;
                        float v0 = in_s[c][p];
                        float v1 = in_s[c][p + 1];
                        float v2 = in_s[c][p + 2];
#pragma unroll
                        for (int q = 0; q < 8; q++)
                            acc[j][q] += v0 * wreg[0][q] + v1 * wreg[1][q] + v2 * wreg[2][q];
                    }
                }
            }
        }
    }

#pragma unroll
    for (int j = 0; j < 4; j++) {
        int ow = ow0 + pg + 32 * j;
        float* op = out + (((size_t)od * HO + oh) * WO + ow) * COUT + og * 8;
        float4 r0, r1;
        r0.x = acc[j][0]; r0.y = acc[j][1]; r0.z = acc[j][2]; r0.w = acc[j][3];
        r1.x = acc[j][4]; r1.y = acc[j][5]; r1.z = acc[j][6]; r1.w = acc[j][7];
        if (do_relu) {
            r0.x = fmaxf(r0.x, 0.f); r0.y = fmaxf(r0.y, 0.f); r0.z = fmaxf(r0.z, 0.f); r0.w = fmaxf(r0.w, 0.f);
            r1.x = fmaxf(r1.x, 0.f); r1.y = fmaxf(r1.y, 0.f); r1.z = fmaxf(r1.z, 0.f); r1.w = fmaxf(r1.w, 0.f);
        }
        ((float4*)op)[0] = r0;
        ((float4*)op)[1] = r1;
    }
}

// ---------------- K5: conv3d 32->1 (no relu) ----------------
__global__ void k_reg2(const float* __restrict__ w2)
{
    __shared__ float ws_t[864];                // [k27][ic32]
    int tid = threadIdx.x;
    for (int i = tid; i < 864; i += 256) {
        int ic = i / 27, k = i % 27;
        ws_t[k * 32 + ic] = w2[i];
    }
    __syncthreads();

    int pos = blockIdx.x * 256 + tid;          // 0 .. 4*256*256
    int ow = pos & 255;
    int r  = pos >> 8;
    int oh = r & 255;
    int od = r >> 8;

    float acc = 0.f;
    for (int kd = 0; kd < 3; kd++) {
        int zd = od + kd - 1;
        if (zd < 0 || zd >= DSLICE) continue;
        for (int kh = 0; kh < 3; kh++) {
            int zh = oh + kh - 1;
            if (zh < 0 || zh >= HO) continue;
            for (int kw = 0; kw < 3; kw++) {
                int zw = ow + kw - 1;
                if (zw < 0 || zw >= WO) continue;
                int k = kd * 9 + kh * 3 + kw;
                const float4* p  = (const float4*)(g_x2 + (((size_t)zd * HO + zh) * WO + zw) * C3);
                const float4* wv = (const float4*)&ws_t[k * 32];
#pragma unroll
                for (int q = 0; q < 8; q++) {
                    float4 a = p[q], b = wv[q];
                    acc += a.x * b.x + a.y * b.y + a.z * b.z + a.w * b.w;
                }
            }
        }
    }
    g_x3[pos] = acc;
}

// ---------------- K6: D-resize 4->8 (jax linear, edge-renormalized) + softmax + expectation ------
__global__ void k_final(float* __restrict__ outp)
{
    int pos = blockIdx.x * 256 + threadIdx.x;  // 0..65535
    float v[4];
#pragma unroll
    for (int d = 0; d < 4; d++) v[d] = g_x3[(size_t)d * (HO * WO) + pos];

    float y[8];
#pragma unroll
    for (int o = 0; o < 8; o++) {
        float s = 0.5f * o - 0.25f;
        int j0 = max(0, (int)ceilf(s - 1.f));
        int j1 = min(3, (int)floorf(s + 1.f));
        float acc = 0.f, wsum = 0.f;
        for (int j = j0; j <= j1; j++) {
            float w = fmaxf(1.f - fabsf(s - (float)j), 0.f);
            acc += w * v[j]; wsum += w;
        }
        y[o] = acc / wsum;
    }
    float m = y[0];
#pragma unroll
    for (int o = 1; o < 8; o++) m = fmaxf(m, y[o]);
    float esum = 0.f, dsum = 0.f;
#pragma unroll
    for (int o = 0; o < 8; o++) {
        float e = expf(y[o] - m);
        esum += e;
        dsum += e * (float)o;
    }
    outp[pos] = dsum / esum;
}

// ---------------- host launch ----------------
extern "C" void kernel_launch(void* const* d_in, const int* in_sizes, int n_in,
                              void* d_out, int out_size)
{
    const float* cams[4] = { (const float*)d_in[0], (const float*)d_in[1],
                             (const float*)d_in[2], (const float*)d_in[3] };
    const float* grids    = (const float*)d_in[4];
    const float* w_feat   = (const float*)d_in[5];
    const float* w_fusion = (const float*)d_in[6];
    const float* w_reg1   = (const float*)d_in[7];
    const float* w_reg2   = (const float*)d_in[8];
    float* out = (float*)d_out;

    float *p_costs, *p_x1, *p_x2, *p_wf, *p_wr1;
    cudaGetSymbolAddress((void**)&p_costs, g_costs);
    cudaGetSymbolAddress((void**)&p_x1,    g_x1);
    cudaGetSymbolAddress((void**)&p_x2,    g_x2);
    cudaGetSymbolAddress((void**)&p_wf,    g_wf_t);
    cudaGetSymbolAddress((void**)&p_wr1,   g_wr1_t);

    // weight transposes
    k_wtrans<<<(C2 * CF * 27 + 255) / 256, 256>>>(w_fusion, 0, C2, CF);
    k_wtrans<<<(C3 * C2 * 27 + 255) / 256, 256>>>(w_reg1,   1, C3, C2);

    // feature extraction (4 cams)
    for (int c = 0; c < 4; c++)
        k_feat<<<dim3(FW / 16, FH / 16), dim3(16, 16)>>>(cams[c], w_feat, c);

    // plane sweep warp
    k_warp<<<dim3(FH * FW / 256, DSLICE, CAMS), 256>>>(grids);

    // antialiased resize -> cost volume (concat over cams in channel dim)
    k_resize<<<dim3(HO, DSLICE, CAMS), WO>>>();

    // 3D conv stack
    k_conv3d<CF, C2><<<dim3(WO / 128, HO, DSLICE), 256>>>(p_costs, p_wf,  p_x1, 1);
    k_conv3d<C2, C3><<<dim3(WO / 128, HO, DSLICE), 128>>>(p_x1,    p_wr1, p_x2, 1);
    k_reg2<<<(DSLICE * HO * WO) / 256, 256>>>(w_reg2);

    // disparity regression
    k_final<<<(HO * WO) / 256, 256>>>(out);
}

// round 3
// speedup vs baseline: 1.6841x; 1.6841x over previous
#include <cuda_runtime.h>
#include <cuda_bf16.h>
#include <cstdint>
#include <math.h>

// ---------------- problem constants ----------------
#define CAMS   4
#define DSLICE 4      // D = NDISP/2
#define NDISP  8
#define IH     640
#define IW     1280
#define FH     320
#define FW     640
#define C1     32
#define HO     256
#define WO     256
#define CF     128    // fused cost channels
#define C2     64
#define C3     32

#define PK1    (CF + 8)    // padded K (elements) conv1
#define PK2    (C2 + 8)    // padded K conv2

// ---------------- scratch (static device memory; no allocs) ----------------
__device__ float g_feat [(size_t)CAMS*FH*FW*C1];            // [cam][y][x][c]
__device__ float g_warp [(size_t)CAMS*DSLICE*FH*FW*C1];     // [cam][d][y][x][c]
__device__ float g_costs[(size_t)DSLICE*HO*WO*CF];          // [d][h][w][c128]
__device__ float g_x1   [(size_t)DSLICE*HO*WO*C2];
__device__ float g_x2   [(size_t)DSLICE*HO*WO*C3];
__device__ float g_x3   [(size_t)DSLICE*HO*WO];
__device__ __nv_bfloat16 g_wB1[27*2*C2*PK1];   // [tap][hi/lo][n][PK1]
__device__ __nv_bfloat16 g_wB2[27*2*C3*PK2];   // [tap][hi/lo][n][PK2]

// =====================================================================
// helpers
// =====================================================================
__device__ __forceinline__ uint32_t smem_u32(const void* p) {
    uint32_t a;
    asm("{ .reg .u64 t; cvta.to.shared.u64 t, %1; cvt.u32.u64 %0, t; }" : "=r"(a) : "l"(p));
    return a;
}
__device__ __forceinline__ uint32_t lds32(uint32_t addr) {
    uint32_t r;
    asm volatile("ld.shared.b32 %0, [%1];" : "=r"(r) : "r"(addr));
    return r;
}
__device__ __forceinline__ void mma_bf16(float& d0, float& d1, float& d2, float& d3,
                                         uint32_t a0, uint32_t a1, uint32_t a2, uint32_t a3,
                                         uint32_t b0, uint32_t b1)
{
    asm volatile(
        "mma.sync.aligned.m16n8k16.row.col.f32.bf16.bf16.f32 "
        "{%0,%1,%2,%3}, {%4,%5,%6,%7}, {%8,%9}, {%0,%1,%2,%3};"
        : "+f"(d0), "+f"(d1), "+f"(d2), "+f"(d3)
        : "r"(a0), "r"(a1), "r"(a2), "r"(a3), "r"(b0), "r"(b1));
}
// pack two floats into bf16x2 (lo -> low half), plus residual pair
__device__ __forceinline__ void split2(float x0, float x1, uint32_t& hi, uint32_t& lo)
{
    __nv_bfloat16 h0 = __float2bfloat16(x0);
    __nv_bfloat16 h1 = __float2bfloat16(x1);
    float r0 = x0 - __bfloat162float(h0);
    float r1 = x1 - __bfloat162float(h1);
    __nv_bfloat162 hp = __halves2bfloat162(h0, h1);
    __nv_bfloat162 lp = __halves2bfloat162(__float2bfloat16(r0), __float2bfloat16(r1));
    hi = *(uint32_t*)&hp;
    lo = *(uint32_t*)&lp;
}

// ---------------- weight prep: bf16 hi/lo B images [tap][hi/lo][n][PK] ----------------
template<int CIN, int COUT, int PK>
__global__ void k_wprep(const float* __restrict__ w, __nv_bfloat16* __restrict__ dst)
{
    int i = blockIdx.x * 256 + threadIdx.x;
    if (i >= 27 * COUT * CIN) return;
    int k = i % CIN;
    int n = (i / CIN) % COUT;
    int t = i / (CIN * COUT);
    int kw = t % 3, kh = (t / 3) % 3, kd = t / 9;
    float v = w[((((size_t)n * CIN + k) * 3 + kd) * 3 + kh) * 3 + kw];
    __nv_bfloat16 h = __float2bfloat16(v);
    __nv_bfloat16 l = __float2bfloat16(v - __bfloat162float(h));
    dst[((size_t)(t * 2 + 0) * COUT + n) * PK + k] = h;
    dst[((size_t)(t * 2 + 1) * COUT + n) * PK + k] = l;
}

// ---------------- K1: conv2d stride2 3->32 + relu, channels-last output ----------------
__global__ void k_feat(const float* __restrict__ cam, const float* __restrict__ w, int cam_idx)
{
    __shared__ float ws[27 * 32];
    int tid = threadIdx.y * 16 + threadIdx.x;
    for (int i = tid; i < 864; i += 256) {
        int k = i >> 5, oc = i & 31;
        ws[i] = w[oc * 27 + k];
    }
    __syncthreads();

    int ow = blockIdx.x * 16 + threadIdx.x;
    int oh = blockIdx.y * 16 + threadIdx.y;

    float v[27];
#pragma unroll
    for (int ic = 0; ic < 3; ic++)
#pragma unroll
        for (int kh = 0; kh < 3; kh++)
#pragma unroll
            for (int kw = 0; kw < 3; kw++) {
                int iy = 2 * oh + kh - 1;
                int ix = 2 * ow + kw - 1;
                float t = 0.f;
                if (iy >= 0 && iy < IH && ix >= 0 && ix < IW)
                    t = cam[(size_t)ic * IH * IW + (size_t)iy * IW + ix];
                v[ic * 9 + kh * 3 + kw] = t;
            }

    float4 acc[8];
#pragma unroll
    for (int q = 0; q < 8; q++) acc[q] = make_float4(0.f, 0.f, 0.f, 0.f);
    const float4* ws4 = (const float4*)ws;
#pragma unroll
    for (int k = 0; k < 27; k++) {
        float vv = v[k];
#pragma unroll
        for (int q = 0; q < 8; q++) {
            float4 wv = ws4[k * 8 + q];
            acc[q].x += vv * wv.x;  acc[q].y += vv * wv.y;
            acc[q].z += vv * wv.z;  acc[q].w += vv * wv.w;
        }
    }
    float4* o = (float4*)(g_feat + ((size_t)cam_idx * FH * FW + (size_t)oh * FW + ow) * C1);
#pragma unroll
    for (int q = 0; q < 8; q++) {
        float4 r = acc[q];
        r.x = fmaxf(r.x, 0.f); r.y = fmaxf(r.y, 0.f);
        r.z = fmaxf(r.z, 0.f); r.w = fmaxf(r.w, 0.f);
        o[q] = r;
    }
}

// ---------------- K2: grid_sample (align_corners=False, zero pad) ----------------
__global__ void k_warp(const float* __restrict__ grids)
{
    int tid = threadIdx.x;
    int pos = blockIdx.x * 256 + tid;
    int d   = blockIdx.y;
    int cam = blockIdx.z;
    int y = pos / FW, x = pos % FW;

    const float* g = grids + ((((size_t)cam * DSLICE + d) * FH + y) * FW + x) * 2;
    float fx = (g[0] + 1.f) * (FW * 0.5f) - 0.5f;
    float fy = (g[1] + 1.f) * (FH * 0.5f) - 0.5f;
    float x0f = floorf(fx), y0f = floorf(fy);
    float wx = fx - x0f,   wy = fy - y0f;
    int x0 = (int)x0f, y0 = (int)y0f;
    int x1 = x0 + 1,   y1 = y0 + 1;
    float vx0 = (x0 >= 0 && x0 < FW) ? 1.f : 0.f;
    float vx1 = (x1 >= 0 && x1 < FW) ? 1.f : 0.f;
    float vy0 = (y0 >= 0 && y0 < FH) ? 1.f : 0.f;
    float vy1 = (y1 >= 0 && y1 < FH) ? 1.f : 0.f;
    float w00 = (1.f - wx) * (1.f - wy) * vx0 * vy0;
    float w01 = wx * (1.f - wy) * vx1 * vy0;
    float w10 = (1.f - wx) * wy * vx0 * vy1;
    float w11 = wx * wy * vx1 * vy1;
    int x0c = min(max(x0, 0), FW - 1), x1c = min(max(x1, 0), FW - 1);
    int y0c = min(max(y0, 0), FH - 1), y1c = min(max(y1, 0), FH - 1);

    const float* fb = g_feat + (size_t)cam * FH * FW * C1;
    const float4* f00 = (const float4*)(fb + ((size_t)y0c * FW + x0c) * C1);
    const float4* f01 = (const float4*)(fb + ((size_t)y0c * FW + x1c) * C1);
    const float4* f10 = (const float4*)(fb + ((size_t)y1c * FW + x0c) * C1);
    const float4* f11 = (const float4*)(fb + ((size_t)y1c * FW + x1c) * C1);
    float4* o = (float4*)(g_warp + ((((size_t)cam * DSLICE + d) * FH + y) * FW + x) * C1);
#pragma unroll
    for (int q = 0; q < 8; q++) {
        float4 a = f00[q], b = f01[q], c = f10[q], e = f11[q];
        float4 r;
        r.x = w00 * a.x + w01 * b.x + w10 * c.x + w11 * e.x;
        r.y = w00 * a.y + w01 * b.y + w10 * c.y + w11 * e.y;
        r.z = w00 * a.z + w01 * b.z + w10 * c.z + w11 * e.z;
        r.w = w00 * a.w + w01 * b.w + w10 * c.w + w11 * e.w;
        o[q] = r;
    }
}

// ---------------- K3: jax.image.resize bilinear (antialias=True) 320x640 -> 256x256 ----------------
__global__ void k_resize()
{
    int wo  = threadIdx.x;
    int ho  = blockIdx.x;
    int d   = blockIdx.y;
    int cam = blockIdx.z;

    float sy = (ho + 0.5f) * 1.25f - 0.5f;
    int jy0 = max((int)ceilf(sy - 1.25f), 0);
    int jy1 = min((int)floorf(sy + 1.25f), FH - 1);
    float wyv[4]; int ny = jy1 - jy0 + 1;
    float sumy = 0.f;
    for (int i = 0; i < ny; i++) {
        float w = fmaxf(1.f - fabsf(sy - (float)(jy0 + i)) * 0.8f, 0.f);
        wyv[i] = w; sumy += w;
    }
    for (int i = 0; i < ny; i++) wyv[i] /= sumy;

    float sx = (wo + 0.5f) * 2.5f - 0.5f;
    int jx0 = max((int)ceilf(sx - 2.5f), 0);
    int jx1 = min((int)floorf(sx + 2.5f), FW - 1);
    float wxv[6]; int nx = jx1 - jx0 + 1;
    float sumx = 0.f;
    for (int i = 0; i < nx; i++) {
        float w = fmaxf(1.f - fabsf(sx - (float)(jx0 + i)) * 0.4f, 0.f);
        wxv[i] = w; sumx += w;
    }
    for (int i = 0; i < nx; i++) wxv[i] /= sumx;

    float4 acc[8];
#pragma unroll
    for (int q = 0; q < 8; q++) acc[q] = make_float4(0.f, 0.f, 0.f, 0.f);

    const float* base = g_warp + ((size_t)cam * DSLICE + d) * (size_t)FH * FW * C1;
    for (int iy = 0; iy < ny; iy++) {
        const float* rowb = base + (size_t)(jy0 + iy) * FW * C1;
        for (int ix = 0; ix < nx; ix++) {
            float wgt = wyv[iy] * wxv[ix];
            const float4* p = (const float4*)(rowb + (size_t)(jx0 + ix) * C1);
#pragma unroll
            for (int q = 0; q < 8; q++) {
                float4 t = p[q];
                acc[q].x += wgt * t.x; acc[q].y += wgt * t.y;
                acc[q].z += wgt * t.z; acc[q].w += wgt * t.w;
            }
        }
    }
    float4* o = (float4*)(g_costs + (((size_t)d * HO + ho) * WO + wo) * CF + cam * C1);
#pragma unroll
    for (int q = 0; q < 8; q++) o[q] = acc[q];
}

// ---------------- K4: conv3d 3x3x3 pad1 + relu via mma.sync bf16 (hi/lo split) ------------
// Block: 256 threads / 8 warps. M=128 positions x N=COUT. K = CIN per tap.
// A staged once per (kd,kh) for 130 positions; kw = row offset q in smem.
// Warp tile: M32 x N(COUT/2). Atoms m16n8k16.
template<int CIN, int COUT>
__global__ void __launch_bounds__(256)
k_conv3d_mma(const float* __restrict__ in, const __nv_bfloat16* __restrict__ wB,
             float* __restrict__ out)
{
    constexpr int PK    = CIN + 8;
    constexpr int PKB   = PK * 2;             // bytes per row
    constexpr int SA    = 130 * PKB;          // one A plane (hi or lo)
    constexpr int NC2   = COUT / 2;           // N per warp
    constexpr int NJ    = NC2 / 8;            // N8 atoms per warp
    constexpr int TAPB  = 2 * COUT * PKB;     // B bytes per tap (hi+lo)
    constexpr int GPR   = CIN / 4;            // float4 groups per A row

    extern __shared__ char dsm[];
    const uint32_t sA  = smem_u32(dsm);
    const uint32_t sAl = sA + SA;
    const uint32_t sB  = sA + 2 * SA;

    int tid  = threadIdx.x;
    int wid  = tid >> 5, lane = tid & 31;
    int gid  = lane >> 2, tig = lane & 3;
    int wM   = wid >> 1;          // 0..3  (M32 group)
    int wN   = wid & 1;           // 0..1  (N half)
    int ow0  = blockIdx.x * 128;
    int oh   = blockIdx.y, od = blockIdx.z;

    float acc[2][NJ][4];
#pragma unroll
    for (int mi = 0; mi < 2; mi++)
#pragma unroll
        for (int nj = 0; nj < NJ; nj++)
#pragma unroll
            for (int c = 0; c < 4; c++) acc[mi][nj][c] = 0.f;

    for (int kd = 0; kd < 3; kd++) {
        int zd = od + kd - 1;
        if (zd < 0 || zd >= DSLICE) continue;
        for (int kh = 0; kh < 3; kh++) {
            int zh = oh + kh - 1;
            if (zh < 0 || zh >= HO) continue;
            const float* inrow = in + ((size_t)zd * HO + zh) * WO * CIN;

            __syncthreads();
            // ---- stage A: 130 positions, hi/lo bf16, padded rows ----
            for (int i = tid; i < 130 * GPR; i += 256) {
                int r = i / GPR, g = i % GPR;
                int p = ow0 - 1 + r;
                float4 v = make_float4(0.f, 0.f, 0.f, 0.f);
                if (p >= 0 && p < WO)
                    v = *(const float4*)(inrow + (size_t)p * CIN + g * 4);
                uint32_t h0, l0, h1, l1;
                split2(v.x, v.y, h0, l0);
                split2(v.z, v.w, h1, l1);
                uint2* dh = (uint2*)(dsm + r * PKB + g * 8);
                uint2* dl = (uint2*)(dsm + SA + r * PKB + g * 8);
                *dh = make_uint2(h0, h1);
                *dl = make_uint2(l0, l1);
            }
            // ---- stage B: flat copy of 3 taps (hi+lo) ----
            {
                int t0 = (kd * 3 + kh) * 3;
                const uint4* src = (const uint4*)(wB + (size_t)t0 * 2 * COUT * PK);
                uint4* dst = (uint4*)(dsm + 2 * SA);
                for (int i = tid; i < 3 * TAPB / 16; i += 256) dst[i] = src[i];
            }
            __syncthreads();

#pragma unroll
            for (int q = 0; q < 3; q++) {
                // per-warp base addresses
                uint32_t aB0 = sA  + (uint32_t)(q + wM * 32 + gid) * PKB + tig * 4;
                uint32_t bBh = sB + q * TAPB + (uint32_t)(wN * NC2 + gid) * PKB + tig * 4;
#pragma unroll
                for (int ks = 0; ks < CIN / 16; ks++) {
                    uint32_t ko = ks * 32;
                    uint32_t ah[2][4], al[2][4];
#pragma unroll
                    for (int mi = 0; mi < 2; mi++) {
                        uint32_t a = aB0 + mi * 16 * PKB + ko;
                        ah[mi][0] = lds32(a);
                        ah[mi][1] = lds32(a + 8 * PKB);
                        ah[mi][2] = lds32(a + 16);
                        ah[mi][3] = lds32(a + 8 * PKB + 16);
                        uint32_t b = a + SA;
                        al[mi][0] = lds32(b);
                        al[mi][1] = lds32(b + 8 * PKB);
                        al[mi][2] = lds32(b + 16);
                        al[mi][3] = lds32(b + 8 * PKB + 16);
                    }
#pragma unroll
                    for (int nj = 0; nj < NJ; nj++) {
                        uint32_t bh = bBh + nj * 8 * PKB + ko;
                        uint32_t bh0 = lds32(bh);
                        uint32_t bh1 = lds32(bh + 16);
                        uint32_t bl0 = lds32(bh + COUT * PKB);
                        uint32_t bl1 = lds32(bh + COUT * PKB + 16);
#pragma unroll
                        for (int mi = 0; mi < 2; mi++) {
                            float* d = acc[mi][nj];
                            mma_bf16(d[0], d[1], d[2], d[3],
                                     ah[mi][0], ah[mi][1], ah[mi][2], ah[mi][3], bh0, bh1);
                            mma_bf16(d[0], d[1], d[2], d[3],
                                     ah[mi][0], ah[mi][1], ah[mi][2], ah[mi][3], bl0, bl1);
                            mma_bf16(d[0], d[1], d[2], d[3],
                                     al[mi][0], al[mi][1], al[mi][2], al[mi][3], bh0, bh1);
                        }
                    }
                }
            }
        }
    }

    // ---- epilogue: relu + store (channels-last) ----
#pragma unroll
    for (int mi = 0; mi < 2; mi++) {
        int row = wM * 32 + mi * 16 + gid;
        float* op0 = out + (((size_t)od * HO + oh) * WO + ow0 + row) * COUT;
        float* op1 = op0 + 8 * COUT;          // row + 8
#pragma unroll
        for (int nj = 0; nj < NJ; nj++) {
            int col = wN * NC2 + nj * 8 + tig * 2;
            float2 r0, r1;
            r0.x = fmaxf(acc[mi][nj][0], 0.f);
            r0.y = fmaxf(acc[mi][nj][1], 0.f);
            r1.x = fmaxf(acc[mi][nj][2], 0.f);
            r1.y = fmaxf(acc[mi][nj][3], 0.f);
            *(float2*)(op0 + col) = r0;
            *(float2*)(op1 + col) = r1;
        }
    }
}

// ---------------- K5: conv3d 32->1 (no relu) ----------------
__global__ void k_reg2(const float* __restrict__ w2)
{
    __shared__ float ws_t[864];
    int tid = threadIdx.x;
    for (int i = tid; i < 864; i += 256) {
        int ic = i / 27, k = i % 27;
        ws_t[k * 32 + ic] = w2[i];
    }
    __syncthreads();

    int pos = blockIdx.x * 256 + tid;
    int ow = pos & 255;
    int r  = pos >> 8;
    int oh = r & 255;
    int od = r >> 8;

    float acc = 0.f;
    for (int kd = 0; kd < 3; kd++) {
        int zd = od + kd - 1;
        if (zd < 0 || zd >= DSLICE) continue;
        for (int kh = 0; kh < 3; kh++) {
            int zh = oh + kh - 1;
            if (zh < 0 || zh >= HO) continue;
            for (int kw = 0; kw < 3; kw++) {
                int zw = ow + kw - 1;
                if (zw < 0 || zw >= WO) continue;
                int k = kd * 9 + kh * 3 + kw;
                const float4* p  = (const float4*)(g_x2 + (((size_t)zd * HO + zh) * WO + zw) * C3);
                const float4* wv = (const float4*)&ws_t[k * 32];
#pragma unroll
                for (int qq = 0; qq < 8; qq++) {
                    float4 a = p[qq], b = wv[qq];
                    acc += a.x * b.x + a.y * b.y + a.z * b.z + a.w * b.w;
                }
            }
        }
    }
    g_x3[pos] = acc;
}

// ---------------- K6: D-resize 4->8 + softmax + expectation ----------------
__global__ void k_final(float* __restrict__ outp)
{
    int pos = blockIdx.x * 256 + threadIdx.x;
    float v[4];
#pragma unroll
    for (int d = 0; d < 4; d++) v[d] = g_x3[(size_t)d * (HO * WO) + pos];

    float y[8];
#pragma unroll
    for (int o = 0; o < 8; o++) {
        float s = 0.5f * o - 0.25f;
        int j0 = max(0, (int)ceilf(s - 1.f));
        int j1 = min(3, (int)floorf(s + 1.f));
        float acc = 0.f, wsum = 0.f;
        for (int j = j0; j <= j1; j++) {
            float w = fmaxf(1.f - fabsf(s - (float)j), 0.f);
            acc += w * v[j]; wsum += w;
        }
        y[o] = acc / wsum;
    }
    float m = y[0];
#pragma unroll
    for (int o = 1; o < 8; o++) m = fmaxf(m, y[o]);
    float esum = 0.f, dsum = 0.f;
#pragma unroll
    for (int o = 0; o < 8; o++) {
        float e = expf(y[o] - m);
        esum += e;
        dsum += e * (float)o;
    }
    outp[pos] = dsum / esum;
}

// ---------------- host launch ----------------
extern "C" void kernel_launch(void* const* d_in, const int* in_sizes, int n_in,
                              void* d_out, int out_size)
{
    const float* cams[4] = { (const float*)d_in[0], (const float*)d_in[1],
                             (const float*)d_in[2], (const float*)d_in[3] };
    const float* grids    = (const float*)d_in[4];
    const float* w_feat   = (const float*)d_in[5];
    const float* w_fusion = (const float*)d_in[6];
    const float* w_reg1   = (const float*)d_in[7];
    const float* w_reg2   = (const float*)d_in[8];
    float* out = (float*)d_out;

    float *p_costs, *p_x1, *p_x2;
    __nv_bfloat16 *p_wB1, *p_wB2;
    cudaGetSymbolAddress((void**)&p_costs, g_costs);
    cudaGetSymbolAddress((void**)&p_x1,    g_x1);
    cudaGetSymbolAddress((void**)&p_x2,    g_x2);
    cudaGetSymbolAddress((void**)&p_wB1,   g_wB1);
    cudaGetSymbolAddress((void**)&p_wB2,   g_wB2);

    // dynamic smem: 2 A planes + 3 taps of B (hi+lo)
    const int SMEM1 = 2 * (130 * PK1 * 2) + 3 * 2 * C2 * PK1 * 2;   // 70720 + 104448 = 175168
    const int SMEM2 = 2 * (130 * PK2 * 2) + 3 * 2 * C3 * PK2 * 2;   // 37440 + 27648  =  65088
    cudaFuncSetAttribute((const void*)k_conv3d_mma<CF, C2>,
                         cudaFuncAttributeMaxDynamicSharedMemorySize, SMEM1);
    cudaFuncSetAttribute((const void*)k_conv3d_mma<C2, C3>,
                         cudaFuncAttributeMaxDynamicSharedMemorySize, SMEM2);

    // weight prep (bf16 hi/lo images)
    k_wprep<CF, C2, PK1><<<(27 * C2 * CF + 255) / 256, 256>>>(w_fusion, p_wB1);
    k_wprep<C2, C3, PK2><<<(27 * C3 * C2 + 255) / 256, 256>>>(w_reg1,   p_wB2);

    // feature extraction (4 cams)
    for (int c = 0; c < 4; c++)
        k_feat<<<dim3(FW / 16, FH / 16), dim3(16, 16)>>>(cams[c], w_feat, c);

    // plane sweep warp
    k_warp<<<dim3(FH * FW / 256, DSLICE, CAMS), 256>>>(grids);

    // antialiased resize -> cost volume
    k_resize<<<dim3(HO, DSLICE, CAMS), WO>>>();

    // 3D conv stack (tensor cores via mma.sync bf16 split)
    k_conv3d_mma<CF, C2><<<dim3(WO / 128, HO, DSLICE), 256, SMEM1>>>(p_costs, p_wB1, p_x1);
    k_conv3d_mma<C2, C3><<<dim3(WO / 128, HO, DSLICE), 256, SMEM2>>>(p_x1, p_wB2, p_x2);
    k_reg2<<<(DSLICE * HO * WO) / 256, 256>>>(w_reg2);

    // disparity regression
    k_final<<<(HO * WO) / 256, 256>>>(out);
}

// round 4
// speedup vs baseline: 2.0638x; 1.2254x over previous
#include <cuda_runtime.h>
#include <cuda_bf16.h>
#include <cstdint>
#include <math.h>

// ---------------- problem constants ----------------
#define CAMS   4
#define DSLICE 4      // D = NDISP/2
#define NDISP  8
#define IH     640
#define IW     1280
#define FH     320
#define FW     640
#define C1     32
#define HO     256
#define WO     256
#define CF     128    // fused cost channels
#define C2     64
#define C3     32

#define PK1    (CF + 8)    // padded K (elements) conv1
#define PK2    (C2 + 8)    // padded K conv2

// ---------------- scratch (static device memory; no allocs) ----------------
__device__ float g_feat [(size_t)CAMS*FH*FW*C1];              // [cam][y][x][c]
__device__ float g_warp [(size_t)CAMS*DSLICE*FH*FW*C1];       // [cam][d][y][x][c]
__device__ __nv_bfloat16 g_costs_h[(size_t)DSLICE*HO*WO*CF];  // hi plane, [d][h][w][c]
__device__ __nv_bfloat16 g_costs_l[(size_t)DSLICE*HO*WO*CF];  // lo plane
__device__ __nv_bfloat16 g_x1_h  [(size_t)DSLICE*HO*WO*C2];
__device__ __nv_bfloat16 g_x1_l  [(size_t)DSLICE*HO*WO*C2];
__device__ float g_x2   [(size_t)DSLICE*HO*WO*C3];
__device__ float g_x3   [(size_t)DSLICE*HO*WO];
__device__ __nv_bfloat16 g_wB1[27*2*C2*PK1];   // [tap][hi/lo][n][PK1]
__device__ __nv_bfloat16 g_wB2[27*2*C3*PK2];   // [tap][hi/lo][n][PK2]

// =====================================================================
// helpers
// =====================================================================
__device__ __forceinline__ uint32_t smem_u32(const void* p) {
    uint32_t a;
    asm("{ .reg .u64 t; cvta.to.shared.u64 t, %1; cvt.u32.u64 %0, t; }" : "=r"(a) : "l"(p));
    return a;
}
__device__ __forceinline__ uint32_t lds32(uint32_t addr) {
    uint32_t r;
    asm volatile("ld.shared.b32 %0, [%1];" : "=r"(r) : "r"(addr));
    return r;
}
__device__ __forceinline__ void cp_async16(uint32_t dst, const void* src, bool valid) {
    int sz = valid ? 16 : 0;
    asm volatile("cp.async.cg.shared.global [%0], [%1], 16, %2;"
                 :: "r"(dst), "l"(src), "r"(sz) : "memory");
}
__device__ __forceinline__ void cp_commit_waitall() {
    asm volatile("cp.async.commit_group;" ::: "memory");
    asm volatile("cp.async.wait_group 0;" ::: "memory");
}
__device__ __forceinline__ void mma_bf16(float& d0, float& d1, float& d2, float& d3,
                                         uint32_t a0, uint32_t a1, uint32_t a2, uint32_t a3,
                                         uint32_t b0, uint32_t b1)
{
    asm volatile(
        "mma.sync.aligned.m16n8k16.row.col.f32.bf16.bf16.f32 "
        "{%0,%1,%2,%3}, {%4,%5,%6,%7}, {%8,%9}, {%0,%1,%2,%3};"
        : "+f"(d0), "+f"(d1), "+f"(d2), "+f"(d3)
        : "r"(a0), "r"(a1), "r"(a2), "r"(a3), "r"(b0), "r"(b1));
}
// pack two floats into bf16x2 hi pair + residual bf16x2 lo pair
__device__ __forceinline__ void split2(float x0, float x1, uint32_t& hi, uint32_t& lo)
{
    __nv_bfloat16 h0 = __float2bfloat16(x0);
    __nv_bfloat16 h1 = __float2bfloat16(x1);
    float r0 = x0 - __bfloat162float(h0);
    float r1 = x1 - __bfloat162float(h1);
    __nv_bfloat162 hp = __halves2bfloat162(h0, h1);
    __nv_bfloat162 lp = __halves2bfloat162(__float2bfloat16(r0), __float2bfloat16(r1));
    hi = *(uint32_t*)&hp;
    lo = *(uint32_t*)&lp;
}

// ---------------- weight prep: bf16 hi/lo B images [tap][hi/lo][n][PK] ----------------
template<int CIN, int COUT, int PK>
__global__ void k_wprep(const float* __restrict__ w, __nv_bfloat16* __restrict__ dst)
{
    int i = blockIdx.x * 256 + threadIdx.x;
    if (i >= 27 * COUT * CIN) return;
    int k = i % CIN;
    int n = (i / CIN) % COUT;
    int t = i / (CIN * COUT);
    int kw = t % 3, kh = (t / 3) % 3, kd = t / 9;
    float v = w[((((size_t)n * CIN + k) * 3 + kd) * 3 + kh) * 3 + kw];
    __nv_bfloat16 h = __float2bfloat16(v);
    __nv_bfloat16 l = __float2bfloat16(v - __bfloat162float(h));
    dst[((size_t)(t * 2 + 0) * COUT + n) * PK + k] = h;
    dst[((size_t)(t * 2 + 1) * COUT + n) * PK + k] = l;
}

// ---------------- K1: conv2d stride2 3->32 + relu (all 4 cams, grid.z=cam) ----------------
__global__ void k_feat4(const float* __restrict__ c0, const float* __restrict__ c1,
                        const float* __restrict__ c2, const float* __restrict__ c3,
                        const float* __restrict__ w)
{
    __shared__ float ws[27 * 32];
    int tid = threadIdx.y * 16 + threadIdx.x;
    for (int i = tid; i < 864; i += 256) {
        int k = i >> 5, oc = i & 31;
        ws[i] = w[oc * 27 + k];
    }
    __syncthreads();

    int cam_idx = blockIdx.z;
    const float* cam = (cam_idx == 0) ? c0 : (cam_idx == 1) ? c1 : (cam_idx == 2) ? c2 : c3;

    int ow = blockIdx.x * 16 + threadIdx.x;
    int oh = blockIdx.y * 16 + threadIdx.y;

    float v[27];
#pragma unroll
    for (int ic = 0; ic < 3; ic++)
#pragma unroll
        for (int kh = 0; kh < 3; kh++)
#pragma unroll
            for (int kw = 0; kw < 3; kw++) {
                int iy = 2 * oh + kh - 1;
                int ix = 2 * ow + kw - 1;
                float t = 0.f;
                if (iy >= 0 && iy < IH && ix >= 0 && ix < IW)
                    t = cam[(size_t)ic * IH * IW + (size_t)iy * IW + ix];
                v[ic * 9 + kh * 3 + kw] = t;
            }

    float4 acc[8];
#pragma unroll
    for (int q = 0; q < 8; q++) acc[q] = make_float4(0.f, 0.f, 0.f, 0.f);
    const float4* ws4 = (const float4*)ws;
#pragma unroll
    for (int k = 0; k < 27; k++) {
        float vv = v[k];
#pragma unroll
        for (int q = 0; q < 8; q++) {
            float4 wv = ws4[k * 8 + q];
            acc[q].x += vv * wv.x;  acc[q].y += vv * wv.y;
            acc[q].z += vv * wv.z;  acc[q].w += vv * wv.w;
        }
    }
    float4* o = (float4*)(g_feat + ((size_t)cam_idx * FH * FW + (size_t)oh * FW + ow) * C1);
#pragma unroll
    for (int q = 0; q < 8; q++) {
        float4 r = acc[q];
        r.x = fmaxf(r.x, 0.f); r.y = fmaxf(r.y, 0.f);
        r.z = fmaxf(r.z, 0.f); r.w = fmaxf(r.w, 0.f);
        o[q] = r;
    }
}

// ---------------- K2: grid_sample (align_corners=False, zero pad) ----------------
__global__ void k_warp(const float* __restrict__ grids)
{
    int tid = threadIdx.x;
    int pos = blockIdx.x * 256 + tid;
    int d   = blockIdx.y;
    int cam = blockIdx.z;
    int y = pos / FW, x = pos % FW;

    const float* g = grids + ((((size_t)cam * DSLICE + d) * FH + y) * FW + x) * 2;
    float fx = (g[0] + 1.f) * (FW * 0.5f) - 0.5f;
    float fy = (g[1] + 1.f) * (FH * 0.5f) - 0.5f;
    float x0f = floorf(fx), y0f = floorf(fy);
    float wx = fx - x0f,   wy = fy - y0f;
    int x0 = (int)x0f, y0 = (int)y0f;
    int x1 = x0 + 1,   y1 = y0 + 1;
    float vx0 = (x0 >= 0 && x0 < FW) ? 1.f : 0.f;
    float vx1 = (x1 >= 0 && x1 < FW) ? 1.f : 0.f;
    float vy0 = (y0 >= 0 && y0 < FH) ? 1.f : 0.f;
    float vy1 = (y1 >= 0 && y1 < FH) ? 1.f : 0.f;
    float w00 = (1.f - wx) * (1.f - wy) * vx0 * vy0;
    float w01 = wx * (1.f - wy) * vx1 * vy0;
    float w10 = (1.f - wx) * wy * vx0 * vy1;
    float w11 = wx * wy * vx1 * vy1;
    int x0c = min(max(x0, 0), FW - 1), x1c = min(max(x1, 0), FW - 1);
    int y0c = min(max(y0, 0), FH - 1), y1c = min(max(y1, 0), FH - 1);

    const float* fb = g_feat + (size_t)cam * FH * FW * C1;
    const float4* f00 = (const float4*)(fb + ((size_t)y0c * FW + x0c) * C1);
    const float4* f01 = (const float4*)(fb + ((size_t)y0c * FW + x1c) * C1);
    const float4* f10 = (const float4*)(fb + ((size_t)y1c * FW + x0c) * C1);
    const float4* f11 = (const float4*)(fb + ((size_t)y1c * FW + x1c) * C1);
    float4* o = (float4*)(g_warp + ((((size_t)cam * DSLICE + d) * FH + y) * FW + x) * C1);
#pragma unroll
    for (int q = 0; q < 8; q++) {
        float4 a = f00[q], b = f01[q], c = f10[q], e = f11[q];
        float4 r;
        r.x = w00 * a.x + w01 * b.x + w10 * c.x + w11 * e.x;
        r.y = w00 * a.y + w01 * b.y + w10 * c.y + w11 * e.y;
        r.z = w00 * a.z + w01 * b.z + w10 * c.z + w11 * e.z;
        r.w = w00 * a.w + w01 * b.w + w10 * c.w + w11 * e.w;
        o[q] = r;
    }
}

// ---------------- K3: antialiased bilinear resize 320x640 -> 256x256, bf16 hi/lo output ----------
__global__ void k_resize()
{
    int wo  = threadIdx.x;
    int ho  = blockIdx.x;
    int d   = blockIdx.y;
    int cam = blockIdx.z;

    float sy = (ho + 0.5f) * 1.25f - 0.5f;
    int jy0 = max((int)ceilf(sy - 1.25f), 0);
    int jy1 = min((int)floorf(sy + 1.25f), FH - 1);
    float wyv[4]; int ny = jy1 - jy0 + 1;
    float sumy = 0.f;
    for (int i = 0; i < ny; i++) {
        float w = fmaxf(1.f - fabsf(sy - (float)(jy0 + i)) * 0.8f, 0.f);
        wyv[i] = w; sumy += w;
    }
    for (int i = 0; i < ny; i++) wyv[i] /= sumy;

    float sx = (wo + 0.5f) * 2.5f - 0.5f;
    int jx0 = max((int)ceilf(sx - 2.5f), 0);
    int jx1 = min((int)floorf(sx + 2.5f), FW - 1);
    float wxv[6]; int nx = jx1 - jx0 + 1;
    float sumx = 0.f;
    for (int i = 0; i < nx; i++) {
        float w = fmaxf(1.f - fabsf(sx - (float)(jx0 + i)) * 0.4f, 0.f);
        wxv[i] = w; sumx += w;
    }
    for (int i = 0; i < nx; i++) wxv[i] /= sumx;

    float4 acc[8];
#pragma unroll
    for (int q = 0; q < 8; q++) acc[q] = make_float4(0.f, 0.f, 0.f, 0.f);

    const float* base = g_warp + ((size_t)cam * DSLICE + d) * (size_t)FH * FW * C1;
    for (int iy = 0; iy < ny; iy++) {
        const float* rowb = base + (size_t)(jy0 + iy) * FW * C1;
        for (int ix = 0; ix < nx; ix++) {
            float wgt = wyv[iy] * wxv[ix];
            const float4* p = (const float4*)(rowb + (size_t)(jx0 + ix) * C1);
#pragma unroll
            for (int q = 0; q < 8; q++) {
                float4 t = p[q];
                acc[q].x += wgt * t.x; acc[q].y += wgt * t.y;
                acc[q].z += wgt * t.z; acc[q].w += wgt * t.w;
            }
        }
    }
    size_t obase = (((size_t)d * HO + ho) * WO + wo) * CF + cam * C1;
#pragma unroll
    for (int q = 0; q < 8; q++) {
        uint32_t h0, l0, h1, l1;
        split2(acc[q].x, acc[q].y, h0, l0);
        split2(acc[q].z, acc[q].w, h1, l1);
        *(uint2*)(g_costs_h + obase + q * 4) = make_uint2(h0, h1);
        *(uint2*)(g_costs_l + obase + q * 4) = make_uint2(l0, l1);
    }
}

// ---------------- K4: conv3d 3x3x3 pad1 + relu via mma.sync bf16 (pre-split inputs) -------
// Block: 256 threads / 8 warps. M=128 positions x N=COUT. K = CIN per tap.
// A (hi/lo planes, bf16 in gmem) staged by pure cp.async copy per (kd,kh); kw = row offset.
template<int CIN, int COUT, bool OBF>
__global__ void __launch_bounds__(256)
k_conv3d_mma(const __nv_bfloat16* __restrict__ in_h, const __nv_bfloat16* __restrict__ in_l,
             const __nv_bfloat16* __restrict__ wB,
             __nv_bfloat16* __restrict__ out_h, __nv_bfloat16* __restrict__ out_l,
             float* __restrict__ out_f)
{
    constexpr int PK    = CIN + 8;
    constexpr int PKB   = PK * 2;             // bytes per smem row
    constexpr int SA    = 130 * PKB;          // one A plane (hi or lo)
    constexpr int NC2   = COUT / 2;           // N per warp
    constexpr int NJ    = NC2 / 8;            // N8 atoms per warp
    constexpr int TAPB  = 2 * COUT * PKB;     // B bytes per tap (hi+lo)
    constexpr int CH    = CIN / 8;            // 16B chunks per A row per plane

    extern __shared__ char dsm[];
    const uint32_t sA = smem_u32(dsm);
    const uint32_t sB = sA + 2 * SA;

    int tid  = threadIdx.x;
    int wid  = tid >> 5, lane = tid & 31;
    int gid  = lane >> 2, tig = lane & 3;
    int wM   = wid >> 1;          // 0..3  (M32 group)
    int wN   = wid & 1;           // 0..1  (N half)
    int ow0  = blockIdx.x * 128;
    int oh   = blockIdx.y, od = blockIdx.z;

    float acc[2][NJ][4];
#pragma unroll
    for (int mi = 0; mi < 2; mi++)
#pragma unroll
        for (int nj = 0; nj < NJ; nj++)
#pragma unroll
            for (int c = 0; c < 4; c++) acc[mi][nj][c] = 0.f;

    for (int kd = 0; kd < 3; kd++) {
        int zd = od + kd - 1;
        if (zd < 0 || zd >= DSLICE) continue;
        for (int kh = 0; kh < 3; kh++) {
            int zh = oh + kh - 1;
            if (zh < 0 || zh >= HO) continue;
            size_t inoff = ((size_t)zd * HO + zh) * WO * CIN;

            __syncthreads();   // protect smem from previous iteration's mma reads
            // ---- stage A: pure copy of hi/lo planes (zero-fill halo) ----
            for (int i = tid; i < 130 * CH; i += 256) {
                int r = i / CH, g = i % CH;
                int p = ow0 - 1 + r;
                bool v = (p >= 0 && p < WO);
                int pc = v ? p : 0;
                size_t so = inoff + (size_t)pc * CIN + g * 8;
                uint32_t doff = (uint32_t)r * PKB + g * 16;
                cp_async16(sA + doff,      in_h + so, v);
                cp_async16(sA + SA + doff, in_l + so, v);
            }
            // ---- stage B: flat copy of 3 taps (hi+lo each) ----
            {
                int t0 = (kd * 3 + kh) * 3;
                const char* src = (const char*)(wB + (size_t)t0 * 2 * COUT * PK);
                for (int i = tid; i < 3 * TAPB / 16; i += 256)
                    cp_async16(sB + i * 16, src + i * 16, true);
            }
            cp_commit_waitall();
            __syncthreads();

#pragma unroll
            for (int q = 0; q < 3; q++) {
                uint32_t aB0 = sA + (uint32_t)(q + wM * 32 + gid) * PKB + tig * 4;
                uint32_t bBh = sB + q * TAPB + (uint32_t)(wN * NC2 + gid) * PKB + tig * 4;
#pragma unroll
                for (int ks = 0; ks < CIN / 16; ks++) {
                    uint32_t ko = ks * 32;
                    uint32_t ah[2][4], al[2][4];
#pragma unroll
                    for (int mi = 0; mi < 2; mi++) {
                        uint32_t a = aB0 + mi * 16 * PKB + ko;
                        ah[mi][0] = lds32(a);
                        ah[mi][1] = lds32(a + 8 * PKB);
                        ah[mi][2] = lds32(a + 16);
                        ah[mi][3] = lds32(a + 8 * PKB + 16);
                        uint32_t b = a + SA;
                        al[mi][0] = lds32(b);
                        al[mi][1] = lds32(b + 8 * PKB);
                        al[mi][2] = lds32(b + 16);
                        al[mi][3] = lds32(b + 8 * PKB + 16);
                    }
#pragma unroll
                    for (int nj = 0; nj < NJ; nj++) {
                        uint32_t bh = bBh + nj * 8 * PKB + ko;
                        uint32_t bh0 = lds32(bh);
                        uint32_t bh1 = lds32(bh + 16);
                        uint32_t bl0 = lds32(bh + COUT * PKB);
                        uint32_t bl1 = lds32(bh + COUT * PKB + 16);
#pragma unroll
                        for (int mi = 0; mi < 2; mi++) {
                            float* d = acc[mi][nj];
                            mma_bf16(d[0], d[1], d[2], d[3],
                                     ah[mi][0], ah[mi][1], ah[mi][2], ah[mi][3], bh0, bh1);
                            mma_bf16(d[0], d[1], d[2], d[3],
                                     ah[mi][0], ah[mi][1], ah[mi][2], ah[mi][3], bl0, bl1);
                            mma_bf16(d[0], d[1], d[2], d[3],
                                     al[mi][0], al[mi][1], al[mi][2], al[mi][3], bh0, bh1);
                        }
                    }
                }
            }
        }
    }

    // ---- epilogue: relu + store ----
#pragma unroll
    for (int mi = 0; mi < 2; mi++) {
        int row = wM * 32 + mi * 16 + gid;
        size_t base0 = (((size_t)od * HO + oh) * WO + ow0 + row) * COUT;
        size_t base1 = base0 + 8 * COUT;      // row + 8
#pragma unroll
        for (int nj = 0; nj < NJ; nj++) {
            int col = wN * NC2 + nj * 8 + tig * 2;
            float v00 = fmaxf(acc[mi][nj][0], 0.f);
            float v01 = fmaxf(acc[mi][nj][1], 0.f);
            float v10 = fmaxf(acc[mi][nj][2], 0.f);
            float v11 = fmaxf(acc[mi][nj][3], 0.f);
            if (OBF) {
                uint32_t h0, l0, h1, l1;
                split2(v00, v01, h0, l0);
                split2(v10, v11, h1, l1);
                *(uint32_t*)(out_h + base0 + col) = h0;
                *(uint32_t*)(out_l + base0 + col) = l0;
                *(uint32_t*)(out_h + base1 + col) = h1;
                *(uint32_t*)(out_l + base1 + col) = l1;
            } else {
                *(float2*)(out_f + base0 + col) = make_float2(v00, v01);
                *(float2*)(out_f + base1 + col) = make_float2(v10, v11);
            }
        }
    }
}

// ---------------- K5: conv3d 32->1 (no relu) ----------------
__global__ void k_reg2(const float* __restrict__ w2)
{
    __shared__ float ws_t[864];
    int tid = threadIdx.x;
    for (int i = tid; i < 864; i += 256) {
        int ic = i / 27, k = i % 27;
        ws_t[k * 32 + ic] = w2[i];
    }
    __syncthreads();

    int pos = blockIdx.x * 256 + tid;
    int ow = pos & 255;
    int r  = pos >> 8;
    int oh = r & 255;
    int od = r >> 8;

    float acc = 0.f;
    for (int kd = 0; kd < 3; kd++) {
        int zd = od + kd - 1;
        if (zd < 0 || zd >= DSLICE) continue;
        for (int kh = 0; kh < 3; kh++) {
            int zh = oh + kh - 1;
            if (zh < 0 || zh >= HO) continue;
            for (int kw = 0; kw < 3; kw++) {
                int zw = ow + kw - 1;
                if (zw < 0 || zw >= WO) continue;
                int k = kd * 9 + kh * 3 + kw;
                const float4* p  = (const float4*)(g_x2 + (((size_t)zd * HO + zh) * WO + zw) * C3);
                const float4* wv = (const float4*)&ws_t[k * 32];
#pragma unroll
                for (int qq = 0; qq < 8; qq++) {
                    float4 a = p[qq], b = wv[qq];
                    acc += a.x * b.x + a.y * b.y + a.z * b.z + a.w * b.w;
                }
            }
        }
    }
    g_x3[pos] = acc;
}

// ---------------- K6: D-resize 4->8 + softmax + expectation ----------------
__global__ void k_final(float* __restrict__ outp)
{
    int pos = blockIdx.x * 256 + threadIdx.x;
    float v[4];
#pragma unroll
    for (int d = 0; d < 4; d++) v[d] = g_x3[(size_t)d * (HO * WO) + pos];

    float y[8];
#pragma unroll
    for (int o = 0; o < 8; o++) {
        float s = 0.5f * o - 0.25f;
        int j0 = max(0, (int)ceilf(s - 1.f));
        int j1 = min(3, (int)floorf(s + 1.f));
        float acc = 0.f, wsum = 0.f;
        for (int j = j0; j <= j1; j++) {
            float w = fmaxf(1.f - fabsf(s - (float)j), 0.f);
            acc += w * v[j]; wsum += w;
        }
        y[o] = acc / wsum;
    }
    float m = y[0];
#pragma unroll
    for (int o = 1; o < 8; o++) m = fmaxf(m, y[o]);
    float esum = 0.f, dsum = 0.f;
#pragma unroll
    for (int o = 0; o < 8; o++) {
        float e = expf(y[o] - m);
        esum += e;
        dsum += e * (float)o;
    }
    outp[pos] = dsum / esum;
}

// ---------------- host launch ----------------
extern "C" void kernel_launch(void* const* d_in, const int* in_sizes, int n_in,
                              void* d_out, int out_size)
{
    const float* cams[4] = { (const float*)d_in[0], (const float*)d_in[1],
                             (const float*)d_in[2], (const float*)d_in[3] };
    const float* grids    = (const float*)d_in[4];
    const float* w_feat   = (const float*)d_in[5];
    const float* w_fusion = (const float*)d_in[6];
    const float* w_reg1   = (const float*)d_in[7];
    const float* w_reg2   = (const float*)d_in[8];
    float* out = (float*)d_out;

    float *p_x2;
    __nv_bfloat16 *p_wB1, *p_wB2, *p_ch, *p_cl, *p_x1h, *p_x1l;
    cudaGetSymbolAddress((void**)&p_x2,  g_x2);
    cudaGetSymbolAddress((void**)&p_wB1, g_wB1);
    cudaGetSymbolAddress((void**)&p_wB2, g_wB2);
    cudaGetSymbolAddress((void**)&p_ch,  g_costs_h);
    cudaGetSymbolAddress((void**)&p_cl,  g_costs_l);
    cudaGetSymbolAddress((void**)&p_x1h, g_x1_h);
    cudaGetSymbolAddress((void**)&p_x1l, g_x1_l);

    // dynamic smem: 2 A planes + 3 taps of B (hi+lo)
    const int SMEM1 = 2 * (130 * PK1 * 2) + 3 * 2 * C2 * PK1 * 2;   // 175168
    const int SMEM2 = 2 * (130 * PK2 * 2) + 3 * 2 * C3 * PK2 * 2;   //  65088
    cudaFuncSetAttribute((const void*)k_conv3d_mma<CF, C2, true>,
                         cudaFuncAttributeMaxDynamicSharedMemorySize, SMEM1);
    cudaFuncSetAttribute((const void*)k_conv3d_mma<C2, C3, false>,
                         cudaFuncAttributeMaxDynamicSharedMemorySize, SMEM2);

    // weight prep (bf16 hi/lo images)
    k_wprep<CF, C2, PK1><<<(27 * C2 * CF + 255) / 256, 256>>>(w_fusion, p_wB1);
    k_wprep<C2, C3, PK2><<<(27 * C3 * C2 + 255) / 256, 256>>>(w_reg1,   p_wB2);

    // feature extraction (all 4 cams in one launch)
    k_feat4<<<dim3(FW / 16, FH / 16, 4), dim3(16, 16)>>>(cams[0], cams[1], cams[2], cams[3], w_feat);

    // plane sweep warp
    k_warp<<<dim3(FH * FW / 256, DSLICE, CAMS), 256>>>(grids);

    // antialiased resize -> bf16 hi/lo cost volume
    k_resize<<<dim3(HO, DSLICE, CAMS), WO>>>();

    // 3D conv stack (tensor cores via mma.sync bf16 split; launch #6 -> ncu capture)
    k_conv3d_mma<CF, C2, true ><<<dim3(WO / 128, HO, DSLICE), 256, SMEM1>>>(p_ch,  p_cl,  p_wB1, p_x1h, p_x1l, nullptr);
    k_conv3d_mma<C2, C3, false><<<dim3(WO / 128, HO, DSLICE), 256, SMEM2>>>(p_x1h, p_x1l, p_wB2, nullptr, nullptr, p_x2);
    k_reg2<<<(DSLICE * HO * WO) / 256, 256>>>(w_reg2);

    // disparity regression
    k_final<<<(HO * WO) / 256, 256>>>(out);
}

// round 5
// speedup vs baseline: 2.8494x; 1.3807x over previous
#include <cuda_runtime.h>
#include <cuda_bf16.h>
#include <cstdint>
#include <math.h>

// ---------------- problem constants ----------------
#define CAMS   4
#define DSLICE 4      // D = NDISP/2
#define NDISP  8
#define IH     640
#define IW     1280
#define FH     320
#define FW     640
#define C1     32
#define HO     256
#define WO     256
#define CF     128    // fused cost channels
#define C2     64
#define C3     32

#define PK1    (CF + 8)    // padded K (elements) conv1
#define PK2    (C2 + 8)    // padded K conv2

// ---------------- scratch (static device memory; no allocs) ----------------
__device__ float g_feat [(size_t)CAMS*FH*FW*C1];              // [cam][y][x][c]
__device__ float g_warp [(size_t)CAMS*DSLICE*FH*FW*C1];       // [cam][d][y][x][c]
__device__ __nv_bfloat16 g_costs_h[(size_t)DSLICE*HO*WO*CF];  // hi plane, [d][h][w][c]
__device__ __nv_bfloat16 g_costs_l[(size_t)DSLICE*HO*WO*CF];  // lo plane
__device__ __nv_bfloat16 g_x1_h  [(size_t)DSLICE*HO*WO*C2];
__device__ __nv_bfloat16 g_x1_l  [(size_t)DSLICE*HO*WO*C2];
__device__ float g_x2   [(size_t)DSLICE*HO*WO*C3];
__device__ float g_x3   [(size_t)DSLICE*HO*WO];
__device__ __nv_bfloat16 g_wB1[27*2*C2*PK1];   // [tap][hi/lo][n][PK1]
__device__ __nv_bfloat16 g_wB2[27*2*C3*PK2];   // [tap][hi/lo][n][PK2]

// =====================================================================
// helpers
// =====================================================================
__device__ __forceinline__ uint32_t smem_u32(const void* p) {
    uint32_t a;
    asm("{ .reg .u64 t; cvta.to.shared.u64 t, %1; cvt.u32.u64 %0, t; }" : "=r"(a) : "l"(p));
    return a;
}
__device__ __forceinline__ uint32_t lds32(uint32_t addr) {
    uint32_t r;
    asm volatile("ld.shared.b32 %0, [%1];" : "=r"(r) : "r"(addr));
    return r;
}
__device__ __forceinline__ void cp_async16(uint32_t dst, const void* src, bool valid) {
    int sz = valid ? 16 : 0;
    asm volatile("cp.async.cg.shared.global [%0], [%1], 16, %2;"
                 :: "r"(dst), "l"(src), "r"(sz) : "memory");
}
__device__ __forceinline__ void cp_commit() {
    asm volatile("cp.async.commit_group;" ::: "memory");
}
__device__ __forceinline__ void cp_wait1() {
    asm volatile("cp.async.wait_group 1;" ::: "memory");
}
__device__ __forceinline__ void cp_wait0() {
    asm volatile("cp.async.wait_group 0;" ::: "memory");
}
__device__ __forceinline__ void mma_bf16(float& d0, float& d1, float& d2, float& d3,
                                         uint32_t a0, uint32_t a1, uint32_t a2, uint32_t a3,
                                         uint32_t b0, uint32_t b1)
{
    asm volatile(
        "mma.sync.aligned.m16n8k16.row.col.f32.bf16.bf16.f32 "
        "{%0,%1,%2,%3}, {%4,%5,%6,%7}, {%8,%9}, {%0,%1,%2,%3};"
        : "+f"(d0), "+f"(d1), "+f"(d2), "+f"(d3)
        : "r"(a0), "r"(a1), "r"(a2), "r"(a3), "r"(b0), "r"(b1));
}
// pack two floats into bf16x2 hi pair + residual bf16x2 lo pair
__device__ __forceinline__ void split2(float x0, float x1, uint32_t& hi, uint32_t& lo)
{
    __nv_bfloat16 h0 = __float2bfloat16(x0);
    __nv_bfloat16 h1 = __float2bfloat16(x1);
    float r0 = x0 - __bfloat162float(h0);
    float r1 = x1 - __bfloat162float(h1);
    __nv_bfloat162 hp = __halves2bfloat162(h0, h1);
    __nv_bfloat162 lp = __halves2bfloat162(__float2bfloat16(r0), __float2bfloat16(r1));
    hi = *(uint32_t*)&hp;
    lo = *(uint32_t*)&lp;
}

// ---------------- weight prep: bf16 hi/lo B images [tap][hi/lo][n][PK] ----------------
template<int CIN, int COUT, int PK>
__global__ void k_wprep(const float* __restrict__ w, __nv_bfloat16* __restrict__ dst)
{
    int i = blockIdx.x * 256 + threadIdx.x;
    if (i >= 27 * COUT * CIN) return;
    int k = i % CIN;
    int n = (i / CIN) % COUT;
    int t = i / (CIN * COUT);
    int kw = t % 3, kh = (t / 3) % 3, kd = t / 9;
    float v = w[((((size_t)n * CIN + k) * 3 + kd) * 3 + kh) * 3 + kw];
    __nv_bfloat16 h = __float2bfloat16(v);
    __nv_bfloat16 l = __float2bfloat16(v - __bfloat162float(h));
    dst[((size_t)(t * 2 + 0) * COUT + n) * PK + k] = h;
    dst[((size_t)(t * 2 + 1) * COUT + n) * PK + k] = l;
}

// ---------------- K1: conv2d stride2 3->32 + relu (all 4 cams, grid.z=cam) ----------------
__global__ void k_feat4(const float* __restrict__ c0, const float* __restrict__ c1,
                        const float* __restrict__ c2, const float* __restrict__ c3,
                        const float* __restrict__ w)
{
    __shared__ float ws[27 * 32];
    int tid = threadIdx.y * 16 + threadIdx.x;
    for (int i = tid; i < 864; i += 256) {
        int k = i >> 5, oc = i & 31;
        ws[i] = w[oc * 27 + k];
    }
    __syncthreads();

    int cam_idx = blockIdx.z;
    const float* cam = (cam_idx == 0) ? c0 : (cam_idx == 1) ? c1 : (cam_idx == 2) ? c2 : c3;

    int ow = blockIdx.x * 16 + threadIdx.x;
    int oh = blockIdx.y * 16 + threadIdx.y;

    float v[27];
#pragma unroll
    for (int ic = 0; ic < 3; ic++)
#pragma unroll
        for (int kh = 0; kh < 3; kh++)
#pragma unroll
            for (int kw = 0; kw < 3; kw++) {
                int iy = 2 * oh + kh - 1;
                int ix = 2 * ow + kw - 1;
                float t = 0.f;
                if (iy >= 0 && iy < IH && ix >= 0 && ix < IW)
                    t = cam[(size_t)ic * IH * IW + (size_t)iy * IW + ix];
                v[ic * 9 + kh * 3 + kw] = t;
            }

    float4 acc[8];
#pragma unroll
    for (int q = 0; q < 8; q++) acc[q] = make_float4(0.f, 0.f, 0.f, 0.f);
    const float4* ws4 = (const float4*)ws;
#pragma unroll
    for (int k = 0; k < 27; k++) {
        float vv = v[k];
#pragma unroll
        for (int q = 0; q < 8; q++) {
            float4 wv = ws4[k * 8 + q];
            acc[q].x += vv * wv.x;  acc[q].y += vv * wv.y;
            acc[q].z += vv * wv.z;  acc[q].w += vv * wv.w;
        }
    }
    float4* o = (float4*)(g_feat + ((size_t)cam_idx * FH * FW + (size_t)oh * FW + ow) * C1);
#pragma unroll
    for (int q = 0; q < 8; q++) {
        float4 r = acc[q];
        r.x = fmaxf(r.x, 0.f); r.y = fmaxf(r.y, 0.f);
        r.z = fmaxf(r.z, 0.f); r.w = fmaxf(r.w, 0.f);
        o[q] = r;
    }
}

// ---------------- K2: grid_sample, warp-cooperative (8 lanes per output pixel) ----------------
// lane c = 16B channel chunk; each tap read = one coalesced-per-pixel LDG.128
__global__ void __launch_bounds__(256)
k_warp(const float* __restrict__ grids)
{
    int tid = threadIdx.x;
    int c   = tid & 7;           // channel chunk (4 floats)
    int pid = tid >> 3;          // pixel within block (0..31)
    int pos = blockIdx.x * 32 + pid;
    int d   = blockIdx.y;
    int cam = blockIdx.z;
    int y = pos / FW, x = pos % FW;

    const float* g = grids + ((((size_t)cam * DSLICE + d) * FH + y) * FW + x) * 2;
    float fx = (g[0] + 1.f) * (FW * 0.5f) - 0.5f;
    float fy = (g[1] + 1.f) * (FH * 0.5f) - 0.5f;
    float x0f = floorf(fx), y0f = floorf(fy);
    float wx = fx - x0f,   wy = fy - y0f;
    int x0 = (int)x0f, y0 = (int)y0f;
    int x1 = x0 + 1,   y1 = y0 + 1;
    float vx0 = (x0 >= 0 && x0 < FW) ? 1.f : 0.f;
    float vx1 = (x1 >= 0 && x1 < FW) ? 1.f : 0.f;
    float vy0 = (y0 >= 0 && y0 < FH) ? 1.f : 0.f;
    float vy1 = (y1 >= 0 && y1 < FH) ? 1.f : 0.f;
    float w00 = (1.f - wx) * (1.f - wy) * vx0 * vy0;
    float w01 = wx * (1.f - wy) * vx1 * vy0;
    float w10 = (1.f - wx) * wy * vx0 * vy1;
    float w11 = wx * wy * vx1 * vy1;
    int x0c = min(max(x0, 0), FW - 1), x1c = min(max(x1, 0), FW - 1);
    int y0c = min(max(y0, 0), FH - 1), y1c = min(max(y1, 0), FH - 1);

    const float* fb = g_feat + (size_t)cam * FH * FW * C1 + c * 4;
    float4 a = *(const float4*)(fb + ((size_t)y0c * FW + x0c) * C1);
    float4 b = *(const float4*)(fb + ((size_t)y0c * FW + x1c) * C1);
    float4 e = *(const float4*)(fb + ((size_t)y1c * FW + x0c) * C1);
    float4 f = *(const float4*)(fb + ((size_t)y1c * FW + x1c) * C1);

    float4 r;
    r.x = w00 * a.x + w01 * b.x + w10 * e.x + w11 * f.x;
    r.y = w00 * a.y + w01 * b.y + w10 * e.y + w11 * f.y;
    r.z = w00 * a.z + w01 * b.z + w10 * e.z + w11 * f.z;
    r.w = w00 * a.w + w01 * b.w + w10 * e.w + w11 * f.w;
    *(float4*)(g_warp + ((size_t)(cam * DSLICE + d) * FH * FW + pos) * C1 + c * 4) = r;
}

// ---------------- K3: antialiased resize, warp-cooperative, bf16 hi/lo output ----------------
__global__ void __launch_bounds__(256)
k_resize()
{
    int tid  = threadIdx.x;
    int c    = tid & 7;
    int pid  = tid >> 3;
    int opos = blockIdx.x * 32 + pid;
    int ho   = opos >> 8;
    int wo   = opos & 255;
    int d    = blockIdx.y;
    int cam  = blockIdx.z;

    float sy = (ho + 0.5f) * 1.25f - 0.5f;
    int jy0 = max((int)ceilf(sy - 1.25f), 0);
    int jy1 = min((int)floorf(sy + 1.25f), FH - 1);
    float wyv[4]; int ny = jy1 - jy0 + 1;
    float sumy = 0.f;
    for (int i = 0; i < ny; i++) {
        float w = fmaxf(1.f - fabsf(sy - (float)(jy0 + i)) * 0.8f, 0.f);
        wyv[i] = w; sumy += w;
    }
    for (int i = 0; i < ny; i++) wyv[i] /= sumy;

    float sx = (wo + 0.5f) * 2.5f - 0.5f;
    int jx0 = max((int)ceilf(sx - 2.5f), 0);
    int jx1 = min((int)floorf(sx + 2.5f), FW - 1);
    float wxv[6]; int nx = jx1 - jx0 + 1;
    float sumx = 0.f;
    for (int i = 0; i < nx; i++) {
        float w = fmaxf(1.f - fabsf(sx - (float)(jx0 + i)) * 0.4f, 0.f);
        wxv[i] = w; sumx += w;
    }
    for (int i = 0; i < nx; i++) wxv[i] /= sumx;

    float4 acc = make_float4(0.f, 0.f, 0.f, 0.f);
    const float* base = g_warp + (size_t)(cam * DSLICE + d) * FH * FW * C1 + c * 4;
    for (int iy = 0; iy < ny; iy++) {
        const float* rowb = base + (size_t)(jy0 + iy) * FW * C1;
        for (int ix = 0; ix < nx; ix++) {
            float wgt = wyv[iy] * wxv[ix];
            float4 t = *(const float4*)(rowb + (size_t)(jx0 + ix) * C1);
            acc.x += wgt * t.x; acc.y += wgt * t.y;
            acc.z += wgt * t.z; acc.w += wgt * t.w;
        }
    }
    size_t obase = (((size_t)d * HO + ho) * WO + wo) * CF + cam * C1 + c * 4;
    uint32_t h0, l0, h1, l1;
    split2(acc.x, acc.y, h0, l0);
    split2(acc.z, acc.w, h1, l1);
    *(uint2*)(g_costs_h + obase) = make_uint2(h0, h1);
    *(uint2*)(g_costs_l + obase) = make_uint2(l0, l1);
}

// ---------------- K4: conv3d 3x3x3 pad1 + relu, mma.sync bf16 split, pipelined staging ------
// Flattened item loop over valid (kd,kh,q). A double-buffered per (kd,kh); B per-tap double-buffered.
template<int CIN, int COUT, bool OBF>
__global__ void __launch_bounds__(256)
k_conv3d_mma(const __nv_bfloat16* __restrict__ in_h, const __nv_bfloat16* __restrict__ in_l,
             const __nv_bfloat16* __restrict__ wB,
             __nv_bfloat16* __restrict__ out_h, __nv_bfloat16* __restrict__ out_l,
             float* __restrict__ out_f)
{
    constexpr int PK  = CIN + 8;
    constexpr int PKB = PK * 2;              // bytes per smem row
    constexpr int SA  = 130 * PKB;           // one A plane (hi or lo)
    constexpr int AB  = 2 * SA;              // A buffer (hi + lo)
    constexpr int TB  = 2 * COUT * PKB;      // one B tap (hi + lo)
    constexpr int NC2 = COUT / 2;
    constexpr int NJ  = NC2 / 8;
    constexpr int CH  = CIN / 8;             // 16B chunks per A row per plane

    extern __shared__ char dsm[];
    const uint32_t sBase = smem_u32(dsm);
    // layout: [A0 | A1 | B0 | B1]
    const uint32_t sA0 = sBase;
    const uint32_t sB0 = sBase + 2 * AB;

    int tid  = threadIdx.x;
    int wid  = tid >> 5, lane = tid & 31;
    int gid  = lane >> 2, tig = lane & 3;
    int wM   = wid >> 1;
    int wN   = wid & 1;
    int ow0  = blockIdx.x * 128;
    int oh   = blockIdx.y, od = blockIdx.z;

    // ---- build valid (kd,kh) list (uniform across block) ----
    int zdv[9], zhv[9], t9v[9];
    int nv = 0;
    for (int kd = 0; kd < 3; kd++) {
        int zd = od + kd - 1;
        if (zd < 0 || zd >= DSLICE) continue;
        for (int kh = 0; kh < 3; kh++) {
            int zh = oh + kh - 1;
            if (zh < 0 || zh >= HO) continue;
            zdv[nv] = zd; zhv[nv] = zh; t9v[nv] = kd * 3 + kh;
            nv++;
        }
    }
    int nitems = nv * 3;

    float acc[2][NJ][4];
#pragma unroll
    for (int mi = 0; mi < 2; mi++)
#pragma unroll
        for (int nj = 0; nj < NJ; nj++)
#pragma unroll
            for (int cc = 0; cc < 4; cc++) acc[mi][nj][cc] = 0.f;

    // ---- staging lambdas ----
    auto stage_A = [&](int slot, int ai) {
        size_t inoff = ((size_t)zdv[ai] * HO + zhv[ai]) * WO * CIN;
        uint32_t dA = sA0 + slot * AB;
        for (int i = tid; i < 130 * CH; i += 256) {
            int r = i / CH, g = i % CH;
            int p = ow0 - 1 + r;
            bool v = (p >= 0 && p < WO);
            int pc = v ? p : 0;
            size_t so = inoff + (size_t)pc * CIN + g * 8;
            uint32_t doff = (uint32_t)r * PKB + g * 16;
            cp_async16(dA + doff,      in_h + so, v);
            cp_async16(dA + SA + doff, in_l + so, v);
        }
    };
    auto stage_B = [&](int slot, int j) {
        int t = t9v[j / 3] * 3 + (j % 3);
        const char* src = (const char*)(wB + (size_t)t * COUT * PK * 2);
        uint32_t dB = sB0 + slot * TB;
        for (int i = tid; i < TB / 16; i += 256)
            cp_async16(dB + i * 16, src + i * 16, true);
    };

    // prologue: stage item 0 (A + B), one commit group
    stage_A(0, 0);
    stage_B(0, 0);
    cp_commit();

    for (int j = 0; j < nitems; j++) {
        int jn = j + 1;
        if (jn < nitems) {
            int an = jn / 3;
            if (jn % 3 == 0) stage_A(an & 1, an);
            stage_B(jn & 1, jn);
        }
        cp_commit();
        if (jn < nitems) cp_wait1(); else cp_wait0();
        __syncthreads();

        int q = j % 3;
        uint32_t dA = sA0 + ((j / 3) & 1) * AB;
        uint32_t dB = sB0 + (j & 1) * TB;
        uint32_t aB0 = dA + (uint32_t)(q + wM * 32 + gid) * PKB + tig * 4;
        uint32_t bB0 = dB + (uint32_t)(wN * NC2 + gid) * PKB + tig * 4;
#pragma unroll
        for (int ks = 0; ks < CIN / 16; ks++) {
            uint32_t ko = ks * 32;
            uint32_t ah[2][4], al[2][4];
#pragma unroll
            for (int mi = 0; mi < 2; mi++) {
                uint32_t a = aB0 + mi * 16 * PKB + ko;
                ah[mi][0] = lds32(a);
                ah[mi][1] = lds32(a + 8 * PKB);
                ah[mi][2] = lds32(a + 16);
                ah[mi][3] = lds32(a + 8 * PKB + 16);
                uint32_t b = a + SA;
                al[mi][0] = lds32(b);
                al[mi][1] = lds32(b + 8 * PKB);
                al[mi][2] = lds32(b + 16);
                al[mi][3] = lds32(b + 8 * PKB + 16);
            }
#pragma unroll
            for (int nj = 0; nj < NJ; nj++) {
                uint32_t bh = bB0 + nj * 8 * PKB + ko;
                uint32_t bh0 = lds32(bh);
                uint32_t bh1 = lds32(bh + 16);
                uint32_t bl0 = lds32(bh + COUT * PKB);
                uint32_t bl1 = lds32(bh + COUT * PKB + 16);
#pragma unroll
                for (int mi = 0; mi < 2; mi++) {
                    float* dd = acc[mi][nj];
                    mma_bf16(dd[0], dd[1], dd[2], dd[3],
                             ah[mi][0], ah[mi][1], ah[mi][2], ah[mi][3], bh0, bh1);
                    mma_bf16(dd[0], dd[1], dd[2], dd[3],
                             ah[mi][0], ah[mi][1], ah[mi][2], ah[mi][3], bl0, bl1);
                    mma_bf16(dd[0], dd[1], dd[2], dd[3],
                             al[mi][0], al[mi][1], al[mi][2], al[mi][3], bh0, bh1);
                }
            }
        }
        __syncthreads();
    }

    // ---- epilogue: relu + store ----
#pragma unroll
    for (int mi = 0; mi < 2; mi++) {
        int row = wM * 32 + mi * 16 + gid;
        size_t base0 = (((size_t)od * HO + oh) * WO + ow0 + row) * COUT;
        size_t base1 = base0 + 8 * COUT;      // row + 8
#pragma unroll
        for (int nj = 0; nj < NJ; nj++) {
            int col = wN * NC2 + nj * 8 + tig * 2;
            float v00 = fmaxf(acc[mi][nj][0], 0.f);
            float v01 = fmaxf(acc[mi][nj][1], 0.f);
            float v10 = fmaxf(acc[mi][nj][2], 0.f);
            float v11 = fmaxf(acc[mi][nj][3], 0.f);
            if (OBF) {
                uint32_t h0, l0, h1, l1;
                split2(v00, v01, h0, l0);
                split2(v10, v11, h1, l1);
                *(uint32_t*)(out_h + base0 + col) = h0;
                *(uint32_t*)(out_l + base0 + col) = l0;
                *(uint32_t*)(out_h + base1 + col) = h1;
                *(uint32_t*)(out_l + base1 + col) = l1;
            } else {
                *(float2*)(out_f + base0 + col) = make_float2(v00, v01);
                *(float2*)(out_f + base1 + col) = make_float2(v10, v11);
            }
        }
    }
}

// ---------------- K5: conv3d 32->1 (no relu) ----------------
__global__ void k_reg2(const float* __restrict__ w2)
{
    __shared__ float ws_t[864];
    int tid = threadIdx.x;
    for (int i = tid; i < 864; i += 256) {
        int ic = i / 27, k = i % 27;
        ws_t[k * 32 + ic] = w2[i];
    }
    __syncthreads();

    int pos = blockIdx.x * 256 + tid;
    int ow = pos & 255;
    int r  = pos >> 8;
    int oh = r & 255;
    int od = r >> 8;

    float acc = 0.f;
    for (int kd = 0; kd < 3; kd++) {
        int zd = od + kd - 1;
        if (zd < 0 || zd >= DSLICE) continue;
        for (int kh = 0; kh < 3; kh++) {
            int zh = oh + kh - 1;
            if (zh < 0 || zh >= HO) continue;
            for (int kw = 0; kw < 3; kw++) {
                int zw = ow + kw - 1;
                if (zw < 0 || zw >= WO) continue;
                int k = kd * 9 + kh * 3 + kw;
                const float4* p  = (const float4*)(g_x2 + (((size_t)zd * HO + zh) * WO + zw) * C3);
                const float4* wv = (const float4*)&ws_t[k * 32];
#pragma unroll
                for (int qq = 0; qq < 8; qq++) {
                    float4 a = p[qq], b = wv[qq];
                    acc += a.x * b.x + a.y * b.y + a.z * b.z + a.w * b.w;
                }
            }
        }
    }
    g_x3[pos] = acc;
}

// ---------------- K6: D-resize 4->8 + softmax + expectation ----------------
__global__ void k_final(float* __restrict__ outp)
{
    int pos = blockIdx.x * 256 + threadIdx.x;
    float v[4];
#pragma unroll
    for (int d = 0; d < 4; d++) v[d] = g_x3[(size_t)d * (HO * WO) + pos];

    float y[8];
#pragma unroll
    for (int o = 0; o < 8; o++) {
        float s = 0.5f * o - 0.25f;
        int j0 = max(0, (int)ceilf(s - 1.f));
        int j1 = min(3, (int)floorf(s + 1.f));
        float acc = 0.f, wsum = 0.f;
        for (int j = j0; j <= j1; j++) {
            float w = fmaxf(1.f - fabsf(s - (float)j), 0.f);
            acc += w * v[j]; wsum += w;
        }
        y[o] = acc / wsum;
    }
    float m = y[0];
#pragma unroll
    for (int o = 1; o < 8; o++) m = fmaxf(m, y[o]);
    float esum = 0.f, dsum = 0.f;
#pragma unroll
    for (int o = 0; o < 8; o++) {
        float e = expf(y[o] - m);
        esum += e;
        dsum += e * (float)o;
    }
    outp[pos] = dsum / esum;
}

// ---------------- host launch ----------------
extern "C" void kernel_launch(void* const* d_in, const int* in_sizes, int n_in,
                              void* d_out, int out_size)
{
    const float* cams[4] = { (const float*)d_in[0], (const float*)d_in[1],
                             (const float*)d_in[2], (const float*)d_in[3] };
    const float* grids    = (const float*)d_in[4];
    const float* w_feat   = (const float*)d_in[5];
    const float* w_fusion = (const float*)d_in[6];
    const float* w_reg1   = (const float*)d_in[7];
    const float* w_reg2   = (const float*)d_in[8];
    float* out = (float*)d_out;

    float *p_x2;
    __nv_bfloat16 *p_wB1, *p_wB2, *p_ch, *p_cl, *p_x1h, *p_x1l;
    cudaGetSymbolAddress((void**)&p_x2,  g_x2);
    cudaGetSymbolAddress((void**)&p_wB1, g_wB1);
    cudaGetSymbolAddress((void**)&p_wB2, g_wB2);
    cudaGetSymbolAddress((void**)&p_ch,  g_costs_h);
    cudaGetSymbolAddress((void**)&p_cl,  g_costs_l);
    cudaGetSymbolAddress((void**)&p_x1h, g_x1_h);
    cudaGetSymbolAddress((void**)&p_x1l, g_x1_l);

    // dynamic smem: 2 A buffers (hi+lo each) + 2 single-tap B buffers (hi+lo each)
    const int SMEM1 = 4 * (130 * PK1 * 2) + 2 * 2 * C2 * PK1 * 2;   // 141440 + 69632 = 211072
    const int SMEM2 = 4 * (130 * PK2 * 2) + 2 * 2 * C3 * PK2 * 2;   //  74880 + 18432 =  93312
    cudaFuncSetAttribute((const void*)k_conv3d_mma<CF, C2, true>,
                         cudaFuncAttributeMaxDynamicSharedMemorySize, SMEM1);
    cudaFuncSetAttribute((const void*)k_conv3d_mma<C2, C3, false>,
                         cudaFuncAttributeMaxDynamicSharedMemorySize, SMEM2);

    // weight prep (bf16 hi/lo images)
    k_wprep<CF, C2, PK1><<<(27 * C2 * CF + 255) / 256, 256>>>(w_fusion, p_wB1);
    k_wprep<C2, C3, PK2><<<(27 * C3 * C2 + 255) / 256, 256>>>(w_reg1,   p_wB2);

    // feature extraction (all 4 cams in one launch)
    k_feat4<<<dim3(FW / 16, FH / 16, 4), dim3(16, 16)>>>(cams[0], cams[1], cams[2], cams[3], w_feat);

    // plane sweep warp (warp-cooperative gather)
    k_warp<<<dim3(FH * FW / 32, DSLICE, CAMS), 256>>>(grids);

    // antialiased resize -> bf16 hi/lo cost volume (warp-cooperative)
    k_resize<<<dim3(HO * WO / 32, DSLICE, CAMS), 256>>>();

    // 3D conv stack (pipelined mma.sync bf16 split; conv1 is launch #6 for ncu)
    k_conv3d_mma<CF, C2, true ><<<dim3(WO / 128, HO, DSLICE), 256, SMEM1>>>(p_ch,  p_cl,  p_wB1, p_x1h, p_x1l, nullptr);
    k_conv3d_mma<C2, C3, false><<<dim3(WO / 128, HO, DSLICE), 256, SMEM2>>>(p_x1h, p_x1l, p_wB2, nullptr, nullptr, p_x2);
    k_reg2<<<(DSLICE * HO * WO) / 256, 256>>>(w_reg2);

    // disparity regression
    k_final<<<(HO * WO) / 256, 256>>>(out);
}

// round 6
// speedup vs baseline: 2.9885x; 1.0488x over previous
#include <cuda_runtime.h>
#include <cuda_bf16.h>
#include <cstdint>
#include <math.h>

// ---------------- problem constants ----------------
#define CAMS   4
#define DSLICE 4      // D = NDISP/2
#define NDISP  8
#define IH     640
#define IW     1280
#define FH     320
#define FW     640
#define C1     32
#define HO     256
#define WO     256
#define CF     128    // fused cost channels
#define C2     64
#define C3     32

#define PK1    (CF + 8)    // padded K (elements) conv1
#define PK2    (C2 + 8)    // padded K conv2

// ---------------- scratch (static device memory; no allocs) ----------------
__device__ float g_feat [(size_t)CAMS*FH*FW*C1];              // [cam][y][x][c]
__device__ float g_warp [(size_t)CAMS*DSLICE*FH*FW*C1];       // [cam][d][y][x][c]
__device__ __nv_bfloat16 g_costs_h[(size_t)DSLICE*HO*WO*CF];  // hi plane, [d][h][w][c]
__device__ __nv_bfloat16 g_costs_l[(size_t)DSLICE*HO*WO*CF];  // lo plane
__device__ __nv_bfloat16 g_x1_h  [(size_t)DSLICE*HO*WO*C2];
__device__ __nv_bfloat16 g_x1_l  [(size_t)DSLICE*HO*WO*C2];
__device__ float g_x2   [(size_t)DSLICE*HO*WO*C3];
__device__ float g_x3   [(size_t)DSLICE*HO*WO];
__device__ __nv_bfloat16 g_wB1[27*2*C2*PK1];   // [tap][hi/lo][n][PK1]
__device__ __nv_bfloat16 g_wB2[27*2*C3*PK2];   // [tap][hi/lo][n][PK2]

// =====================================================================
// helpers
// =====================================================================
__device__ __forceinline__ uint32_t smem_u32(const void* p) {
    uint32_t a;
    asm("{ .reg .u64 t; cvta.to.shared.u64 t, %1; cvt.u32.u64 %0, t; }" : "=r"(a) : "l"(p));
    return a;
}
__device__ __forceinline__ uint32_t lds32(uint32_t addr) {
    uint32_t r;
    asm volatile("ld.shared.b32 %0, [%1];" : "=r"(r) : "r"(addr));
    return r;
}
__device__ __forceinline__ void cp_async16(uint32_t dst, const void* src, bool valid) {
    int sz = valid ? 16 : 0;
    asm volatile("cp.async.cg.shared.global [%0], [%1], 16, %2;"
                 :: "r"(dst), "l"(src), "r"(sz) : "memory");
}
__device__ __forceinline__ void cp_commit() {
    asm volatile("cp.async.commit_group;" ::: "memory");
}
__device__ __forceinline__ void cp_wait1() {
    asm volatile("cp.async.wait_group 1;" ::: "memory");
}
__device__ __forceinline__ void cp_wait0() {
    asm volatile("cp.async.wait_group 0;" ::: "memory");
}
__device__ __forceinline__ void mma_bf16(float& d0, float& d1, float& d2, float& d3,
                                         uint32_t a0, uint32_t a1, uint32_t a2, uint32_t a3,
                                         uint32_t b0, uint32_t b1)
{
    asm volatile(
        "mma.sync.aligned.m16n8k16.row.col.f32.bf16.bf16.f32 "
        "{%0,%1,%2,%3}, {%4,%5,%6,%7}, {%8,%9}, {%0,%1,%2,%3};"
        : "+f"(d0), "+f"(d1), "+f"(d2), "+f"(d3)
        : "r"(a0), "r"(a1), "r"(a2), "r"(a3), "r"(b0), "r"(b1));
}
// pack two floats into bf16x2 hi pair + residual bf16x2 lo pair
__device__ __forceinline__ void split2(float x0, float x1, uint32_t& hi, uint32_t& lo)
{
    __nv_bfloat16 h0 = __float2bfloat16(x0);
    __nv_bfloat16 h1 = __float2bfloat16(x1);
    float r0 = x0 - __bfloat162float(h0);
    float r1 = x1 - __bfloat162float(h1);
    __nv_bfloat162 hp = __halves2bfloat162(h0, h1);
    __nv_bfloat162 lp = __halves2bfloat162(__float2bfloat16(r0), __float2bfloat16(r1));
    hi = *(uint32_t*)&hp;
    lo = *(uint32_t*)&lp;
}

// ---------------- weight prep: bf16 hi/lo B images [tap][hi/lo][n][PK] ----------------
template<int CIN, int COUT, int PK>
__global__ void k_wprep(const float* __restrict__ w, __nv_bfloat16* __restrict__ dst)
{
    int i = blockIdx.x * 256 + threadIdx.x;
    if (i >= 27 * COUT * CIN) return;
    int k = i % CIN;
    int n = (i / CIN) % COUT;
    int t = i / (CIN * COUT);
    int kw = t % 3, kh = (t / 3) % 3, kd = t / 9;
    float v = w[((((size_t)n * CIN + k) * 3 + kd) * 3 + kh) * 3 + kw];
    __nv_bfloat16 h = __float2bfloat16(v);
    __nv_bfloat16 l = __float2bfloat16(v - __bfloat162float(h));
    dst[((size_t)(t * 2 + 0) * COUT + n) * PK + k] = h;
    dst[((size_t)(t * 2 + 1) * COUT + n) * PK + k] = l;
}

// ---------------- K1: conv2d stride2 3->32 + relu (all 4 cams, grid.z=cam) ----------------
__global__ void k_feat4(const float* __restrict__ c0, const float* __restrict__ c1,
                        const float* __restrict__ c2, const float* __restrict__ c3,
                        const float* __restrict__ w)
{
    __shared__ float ws[27 * 32];
    int tid = threadIdx.y * 16 + threadIdx.x;
    for (int i = tid; i < 864; i += 256) {
        int k = i >> 5, oc = i & 31;
        ws[i] = w[oc * 27 + k];
    }
    __syncthreads();

    int cam_idx = blockIdx.z;
    const float* cam = (cam_idx == 0) ? c0 : (cam_idx == 1) ? c1 : (cam_idx == 2) ? c2 : c3;

    int ow = blockIdx.x * 16 + threadIdx.x;
    int oh = blockIdx.y * 16 + threadIdx.y;

    float v[27];
#pragma unroll
    for (int ic = 0; ic < 3; ic++)
#pragma unroll
        for (int kh = 0; kh < 3; kh++)
#pragma unroll
            for (int kw = 0; kw < 3; kw++) {
                int iy = 2 * oh + kh - 1;
                int ix = 2 * ow + kw - 1;
                float t = 0.f;
                if (iy >= 0 && iy < IH && ix >= 0 && ix < IW)
                    t = cam[(size_t)ic * IH * IW + (size_t)iy * IW + ix];
                v[ic * 9 + kh * 3 + kw] = t;
            }

    float4 acc[8];
#pragma unroll
    for (int q = 0; q < 8; q++) acc[q] = make_float4(0.f, 0.f, 0.f, 0.f);
    const float4* ws4 = (const float4*)ws;
#pragma unroll
    for (int k = 0; k < 27; k++) {
        float vv = v[k];
#pragma unroll
        for (int q = 0; q < 8; q++) {
            float4 wv = ws4[k * 8 + q];
            acc[q].x += vv * wv.x;  acc[q].y += vv * wv.y;
            acc[q].z += vv * wv.z;  acc[q].w += vv * wv.w;
        }
    }
    float4* o = (float4*)(g_feat + ((size_t)cam_idx * FH * FW + (size_t)oh * FW + ow) * C1);
#pragma unroll
    for (int q = 0; q < 8; q++) {
        float4 r = acc[q];
        r.x = fmaxf(r.x, 0.f); r.y = fmaxf(r.y, 0.f);
        r.z = fmaxf(r.z, 0.f); r.w = fmaxf(r.w, 0.f);
        o[q] = r;
    }
}

// ---------------- K2: grid_sample, warp-cooperative (8 lanes per output pixel) ----------------
__global__ void __launch_bounds__(256)
k_warp(const float* __restrict__ grids)
{
    int tid = threadIdx.x;
    int c   = tid & 7;           // channel chunk (4 floats)
    int pid = tid >> 3;          // pixel within block (0..31)
    int pos = blockIdx.x * 32 + pid;
    int d   = blockIdx.y;
    int cam = blockIdx.z;
    int y = pos / FW, x = pos % FW;

    const float* g = grids + ((((size_t)cam * DSLICE + d) * FH + y) * FW + x) * 2;
    float fx = (g[0] + 1.f) * (FW * 0.5f) - 0.5f;
    float fy = (g[1] + 1.f) * (FH * 0.5f) - 0.5f;
    float x0f = floorf(fx), y0f = floorf(fy);
    float wx = fx - x0f,   wy = fy - y0f;
    int x0 = (int)x0f, y0 = (int)y0f;
    int x1 = x0 + 1,   y1 = y0 + 1;
    float vx0 = (x0 >= 0 && x0 < FW) ? 1.f : 0.f;
    float vx1 = (x1 >= 0 && x1 < FW) ? 1.f : 0.f;
    float vy0 = (y0 >= 0 && y0 < FH) ? 1.f : 0.f;
    float vy1 = (y1 >= 0 && y1 < FH) ? 1.f : 0.f;
    float w00 = (1.f - wx) * (1.f - wy) * vx0 * vy0;
    float w01 = wx * (1.f - wy) * vx1 * vy0;
    float w10 = (1.f - wx) * wy * vx0 * vy1;
    float w11 = wx * wy * vx1 * vy1;
    int x0c = min(max(x0, 0), FW - 1), x1c = min(max(x1, 0), FW - 1);
    int y0c = min(max(y0, 0), FH - 1), y1c = min(max(y1, 0), FH - 1);

    const float* fb = g_feat + (size_t)cam * FH * FW * C1 + c * 4;
    float4 a = *(const float4*)(fb + ((size_t)y0c * FW + x0c) * C1);
    float4 b = *(const float4*)(fb + ((size_t)y0c * FW + x1c) * C1);
    float4 e = *(const float4*)(fb + ((size_t)y1c * FW + x0c) * C1);
    float4 f = *(const float4*)(fb + ((size_t)y1c * FW + x1c) * C1);

    float4 r;
    r.x = w00 * a.x + w01 * b.x + w10 * e.x + w11 * f.x;
    r.y = w00 * a.y + w01 * b.y + w10 * e.y + w11 * f.y;
    r.z = w00 * a.z + w01 * b.z + w10 * e.z + w11 * f.z;
    r.w = w00 * a.w + w01 * b.w + w10 * e.w + w11 * f.w;
    *(float4*)(g_warp + ((size_t)(cam * DSLICE + d) * FH * FW + pos) * C1 + c * 4) = r;
}

// ---------------- K3: antialiased resize, warp-cooperative, bf16 hi/lo output ----------------
__global__ void __launch_bounds__(256)
k_resize()
{
    int tid  = threadIdx.x;
    int c    = tid & 7;
    int pid  = tid >> 3;
    int opos = blockIdx.x * 32 + pid;
    int ho   = opos >> 8;
    int wo   = opos & 255;
    int d    = blockIdx.y;
    int cam  = blockIdx.z;

    float sy = (ho + 0.5f) * 1.25f - 0.5f;
    int jy0 = max((int)ceilf(sy - 1.25f), 0);
    int jy1 = min((int)floorf(sy + 1.25f), FH - 1);
    float wyv[4]; int ny = jy1 - jy0 + 1;
    float sumy = 0.f;
    for (int i = 0; i < ny; i++) {
        float w = fmaxf(1.f - fabsf(sy - (float)(jy0 + i)) * 0.8f, 0.f);
        wyv[i] = w; sumy += w;
    }
    for (int i = 0; i < ny; i++) wyv[i] /= sumy;

    float sx = (wo + 0.5f) * 2.5f - 0.5f;
    int jx0 = max((int)ceilf(sx - 2.5f), 0);
    int jx1 = min((int)floorf(sx + 2.5f), FW - 1);
    float wxv[6]; int nx = jx1 - jx0 + 1;
    float sumx = 0.f;
    for (int i = 0; i < nx; i++) {
        float w = fmaxf(1.f - fabsf(sx - (float)(jx0 + i)) * 0.4f, 0.f);
        wxv[i] = w; sumx += w;
    }
    for (int i = 0; i < nx; i++) wxv[i] /= sumx;

    float4 acc = make_float4(0.f, 0.f, 0.f, 0.f);
    const float* base = g_warp + (size_t)(cam * DSLICE + d) * FH * FW * C1 + c * 4;
    for (int iy = 0; iy < ny; iy++) {
        const float* rowb = base + (size_t)(jy0 + iy) * FW * C1;
        for (int ix = 0; ix < nx; ix++) {
            float wgt = wyv[iy] * wxv[ix];
            float4 t = *(const float4*)(rowb + (size_t)(jx0 + ix) * C1);
            acc.x += wgt * t.x; acc.y += wgt * t.y;
            acc.z += wgt * t.z; acc.w += wgt * t.w;
        }
    }
    size_t obase = (((size_t)d * HO + ho) * WO + wo) * CF + cam * C1 + c * 4;
    uint32_t h0, l0, h1, l1;
    split2(acc.x, acc.y, h0, l0);
    split2(acc.z, acc.w, h1, l1);
    *(uint2*)(g_costs_h + obase) = make_uint2(h0, h1);
    *(uint2*)(g_costs_l + obase) = make_uint2(l0, l1);
}

// ---------------- K4: conv3d 3x3x3 pad1 + relu, mma.sync bf16 split, pipelined staging ------
// 128 threads / 4 warps. Warp tile = (MI*16) x 32 from block M128 x N(32*NWN).
// conv1: MI=4, NWN=2 (warp M64xN32). conv2: MI=2, NWN=1 (warp M32xN32).
template<int CIN, int COUT, int MI, int NWN, bool OBF>
__global__ void __launch_bounds__(128)
k_conv3d_mma(const __nv_bfloat16* __restrict__ in_h, const __nv_bfloat16* __restrict__ in_l,
             const __nv_bfloat16* __restrict__ wB,
             __nv_bfloat16* __restrict__ out_h, __nv_bfloat16* __restrict__ out_l,
             float* __restrict__ out_f)
{
    constexpr int NT  = 128;
    constexpr int PK  = CIN + 8;
    constexpr int PKB = PK * 2;              // bytes per smem row
    constexpr int SA  = 130 * PKB;           // one A plane (hi or lo)
    constexpr int AB  = 2 * SA;              // A buffer (hi + lo)
    constexpr int TB  = 2 * COUT * PKB;      // one B tap (hi + lo)
    constexpr int NJ  = (COUT / NWN) / 8;    // 4 for both convs
    constexpr int CH  = CIN / 8;             // 16B chunks per A row per plane

    extern __shared__ char dsm[];
    const uint32_t sBase = smem_u32(dsm);
    const uint32_t sA0 = sBase;              // [A0 | A1 | B0 | B1]
    const uint32_t sB0 = sBase + 2 * AB;

    int tid  = threadIdx.x;
    int wid  = tid >> 5, lane = tid & 31;
    int gid  = lane >> 2, tig = lane & 3;
    int wM   = wid / NWN;                    // M tile index (MI*16 rows each)
    int wN   = wid % NWN;                    // N32 half
    int ow0  = blockIdx.x * 128;
    int oh   = blockIdx.y, od = blockIdx.z;

    // ---- build valid (kd,kh) list (uniform across block) ----
    int zdv[9], zhv[9], t9v[9];
    int nv = 0;
    for (int kd = 0; kd < 3; kd++) {
        int zd = od + kd - 1;
        if (zd < 0 || zd >= DSLICE) continue;
        for (int kh = 0; kh < 3; kh++) {
            int zh = oh + kh - 1;
            if (zh < 0 || zh >= HO) continue;
            zdv[nv] = zd; zhv[nv] = zh; t9v[nv] = kd * 3 + kh;
            nv++;
        }
    }
    int nitems = nv * 3;

    float acc[MI][NJ][4];
#pragma unroll
    for (int mi = 0; mi < MI; mi++)
#pragma unroll
        for (int nj = 0; nj < NJ; nj++)
#pragma unroll
            for (int cc = 0; cc < 4; cc++) acc[mi][nj][cc] = 0.f;

    // ---- staging lambdas ----
    auto stage_A = [&](int slot, int ai) {
        size_t inoff = ((size_t)zdv[ai] * HO + zhv[ai]) * WO * CIN;
        uint32_t dA = sA0 + slot * AB;
        for (int i = tid; i < 130 * CH; i += NT) {
            int r = i / CH, g = i % CH;
            int p = ow0 - 1 + r;
            bool v = (p >= 0 && p < WO);
            int pc = v ? p : 0;
            size_t so = inoff + (size_t)pc * CIN + g * 8;
            uint32_t doff = (uint32_t)r * PKB + g * 16;
            cp_async16(dA + doff,      in_h + so, v);
            cp_async16(dA + SA + doff, in_l + so, v);
        }
    };
    auto stage_B = [&](int slot, int j) {
        int t = t9v[j / 3] * 3 + (j % 3);
        const char* src = (const char*)(wB + (size_t)t * COUT * PK * 2);
        uint32_t dB = sB0 + slot * TB;
        for (int i = tid; i < TB / 16; i += NT)
            cp_async16(dB + i * 16, src + i * 16, true);
    };

    // prologue: stage item 0 (A + B), one commit group
    stage_A(0, 0);
    stage_B(0, 0);
    cp_commit();

    for (int j = 0; j < nitems; j++) {
        int jn = j + 1;
        if (jn < nitems) {
            int an = jn / 3;
            if (jn % 3 == 0) stage_A(an & 1, an);
            stage_B(jn & 1, jn);
        }
        cp_commit();
        if (jn < nitems) cp_wait1(); else cp_wait0();
        __syncthreads();

        int q = j % 3;
        uint32_t dA = sA0 + ((j / 3) & 1) * AB;
        uint32_t dB = sB0 + (j & 1) * TB;
        uint32_t aB0 = dA + (uint32_t)(q + wM * (MI * 16) + gid) * PKB + tig * 4;
        uint32_t bB0 = dB + (uint32_t)(wN * 32 + gid) * PKB + tig * 4;
#pragma unroll
        for (int ks = 0; ks < CIN / 16; ks++) {
            uint32_t ko = ks * 32;
            uint32_t ah[MI][4], al[MI][4];
#pragma unroll
            for (int mi = 0; mi < MI; mi++) {
                uint32_t a = aB0 + mi * 16 * PKB + ko;
                ah[mi][0] = lds32(a);
                ah[mi][1] = lds32(a + 8 * PKB);
                ah[mi][2] = lds32(a + 16);
                ah[mi][3] = lds32(a + 8 * PKB + 16);
                uint32_t b = a + SA;
                al[mi][0] = lds32(b);
                al[mi][1] = lds32(b + 8 * PKB);
                al[mi][2] = lds32(b + 16);
                al[mi][3] = lds32(b + 8 * PKB + 16);
            }
#pragma unroll
            for (int nj = 0; nj < NJ; nj++) {
                uint32_t bh = bB0 + nj * 8 * PKB + ko;
                uint32_t bh0 = lds32(bh);
                uint32_t bh1 = lds32(bh + 16);
                uint32_t bl0 = lds32(bh + COUT * PKB);
                uint32_t bl1 = lds32(bh + COUT * PKB + 16);
#pragma unroll
                for (int mi = 0; mi < MI; mi++) {
                    float* dd = acc[mi][nj];
                    mma_bf16(dd[0], dd[1], dd[2], dd[3],
                             ah[mi][0], ah[mi][1], ah[mi][2], ah[mi][3], bh0, bh1);
                    mma_bf16(dd[0], dd[1], dd[2], dd[3],
                             ah[mi][0], ah[mi][1], ah[mi][2], ah[mi][3], bl0, bl1);
                    mma_bf16(dd[0], dd[1], dd[2], dd[3],
                             al[mi][0], al[mi][1], al[mi][2], al[mi][3], bh0, bh1);
                }
            }
        }
        __syncthreads();
    }

    // ---- epilogue: relu + store ----
#pragma unroll
    for (int mi = 0; mi < MI; mi++) {
        int row = wM * (MI * 16) + mi * 16 + gid;
        size_t base0 = (((size_t)od * HO + oh) * WO + ow0 + row) * COUT;
        size_t base1 = base0 + 8 * COUT;      // row + 8
#pragma unroll
        for (int nj = 0; nj < NJ; nj++) {
            int col = wN * 32 + nj * 8 + tig * 2;
            float v00 = fmaxf(acc[mi][nj][0], 0.f);
            float v01 = fmaxf(acc[mi][nj][1], 0.f);
            float v10 = fmaxf(acc[mi][nj][2], 0.f);
            float v11 = fmaxf(acc[mi][nj][3], 0.f);
            if (OBF) {
                uint32_t h0, l0, h1, l1;
                split2(v00, v01, h0, l0);
                split2(v10, v11, h1, l1);
                *(uint32_t*)(out_h + base0 + col) = h0;
                *(uint32_t*)(out_l + base0 + col) = l0;
                *(uint32_t*)(out_h + base1 + col) = h1;
                *(uint32_t*)(out_l + base1 + col) = l1;
            } else {
                *(float2*)(out_f + base0 + col) = make_float2(v00, v01);
                *(float2*)(out_f + base1 + col) = make_float2(v10, v11);
            }
        }
    }
}

// ---------------- K5: conv3d 32->1 (no relu), smem-tiled ----------------
// Block: 32x8 outputs. Per kd: stage 34x10x32 input plane via cp.async.
__global__ void __launch_bounds__(256)
k_reg2(const float* __restrict__ w2)
{
    __shared__ float ws_t[27 * 32];                 // [k27][ic32]
    __shared__ float tile[10][34][32];              // [zh][zw][c]
    int tx = threadIdx.x & 31;                      // output w
    int ty = threadIdx.x >> 5;                      // output h
    int tid = threadIdx.x;
    for (int i = tid; i < 864; i += 256) {
        int ic = i / 27, k = i % 27;
        ws_t[k * 32 + ic] = w2[i];
    }

    int ow0 = blockIdx.x * 32;
    int oh0 = blockIdx.y * 8;
    int od  = blockIdx.z;
    int ow = ow0 + tx, oh = oh0 + ty;

    float acc = 0.f;
    for (int kd = 0; kd < 3; kd++) {
        int zd = od + kd - 1;
        if (zd < 0 || zd >= DSLICE) continue;
        __syncthreads();
        // stage plane: zh in [oh0-1, oh0+8], zw in [ow0-1, ow0+32]
        // 10*34*32 floats = 10*34*8 chunks of 16B = 2720 chunks
        for (int i = tid; i < 10 * 34 * 8; i += 256) {
            int g  = i & 7;
            int zw = (i >> 3) % 34 + ow0 - 1;
            int zh = (i >> 3) / 34 + oh0 - 1;
            bool v = (zw >= 0 && zw < WO && zh >= 0 && zh < HO);
            int zwc = v ? zw : 0, zhc = v ? zh : 0;
            const float* src = g_x2 + (((size_t)zd * HO + zhc) * WO + zwc) * C3 + g * 4;
            cp_async16(smem_u32(&tile[(i >> 3) / 34][(i >> 3) % 34][g * 4]), src, v);
        }
        cp_commit();
        cp_wait0();
        __syncthreads();

#pragma unroll
        for (int kh = 0; kh < 3; kh++) {
#pragma unroll
            for (int kw = 0; kw < 3; kw++) {
                int k = kd * 9 + kh * 3 + kw;
                const float4* p  = (const float4*)&tile[ty + kh][tx + kw][0];
                const float4* wv = (const float4*)&ws_t[k * 32];
#pragma unroll
                for (int qq = 0; qq < 8; qq++) {
                    float4 a = p[qq], b = wv[qq];
                    acc += a.x * b.x + a.y * b.y + a.z * b.z + a.w * b.w;
                }
            }
        }
    }
    g_x3[((size_t)od * HO + oh) * WO + ow] = acc;
}

// ---------------- K6: D-resize 4->8 + softmax + expectation ----------------
__global__ void k_final(float* __restrict__ outp)
{
    int pos = blockIdx.x * 256 + threadIdx.x;
    float v[4];
#pragma unroll
    for (int d = 0; d < 4; d++) v[d] = g_x3[(size_t)d * (HO * WO) + pos];

    float y[8];
#pragma unroll
    for (int o = 0; o < 8; o++) {
        float s = 0.5f * o - 0.25f;
        int j0 = max(0, (int)ceilf(s - 1.f));
        int j1 = min(3, (int)floorf(s + 1.f));
        float acc = 0.f, wsum = 0.f;
        for (int j = j0; j <= j1; j++) {
            float w = fmaxf(1.f - fabsf(s - (float)j), 0.f);
            acc += w * v[j]; wsum += w;
        }
        y[o] = acc / wsum;
    }
    float m = y[0];
#pragma unroll
    for (int o = 1; o < 8; o++) m = fmaxf(m, y[o]);
    float esum = 0.f, dsum = 0.f;
#pragma unroll
    for (int o = 0; o < 8; o++) {
        float e = expf(y[o] - m);
        esum += e;
        dsum += e * (float)o;
    }
    outp[pos] = dsum / esum;
}

// ---------------- host launch ----------------
extern "C" void kernel_launch(void* const* d_in, const int* in_sizes, int n_in,
                              void* d_out, int out_size)
{
    const float* cams[4] = { (const float*)d_in[0], (const float*)d_in[1],
                             (const float*)d_in[2], (const float*)d_in[3] };
    const float* grids    = (const float*)d_in[4];
    const float* w_feat   = (const float*)d_in[5];
    const float* w_fusion = (const float*)d_in[6];
    const float* w_reg1   = (const float*)d_in[7];
    const float* w_reg2   = (const float*)d_in[8];
    float* out = (float*)d_out;

    __nv_bfloat16 *p_wB1, *p_wB2, *p_ch, *p_cl, *p_x1h, *p_x1l;
    float* p_x2;
    cudaGetSymbolAddress((void**)&p_x2,  g_x2);
    cudaGetSymbolAddress((void**)&p_wB1, g_wB1);
    cudaGetSymbolAddress((void**)&p_wB2, g_wB2);
    cudaGetSymbolAddress((void**)&p_ch,  g_costs_h);
    cudaGetSymbolAddress((void**)&p_cl,  g_costs_l);
    cudaGetSymbolAddress((void**)&p_x1h, g_x1_h);
    cudaGetSymbolAddress((void**)&p_x1l, g_x1_l);

    // dynamic smem: 2 A buffers (hi+lo each) + 2 single-tap B buffers (hi+lo each)
    const int SMEM1 = 4 * (130 * PK1 * 2) + 2 * 2 * C2 * PK1 * 2;   // 211072
    const int SMEM2 = 4 * (130 * PK2 * 2) + 2 * 2 * C3 * PK2 * 2;   //  93312
    cudaFuncSetAttribute((const void*)k_conv3d_mma<CF, C2, 4, 2, true>,
                         cudaFuncAttributeMaxDynamicSharedMemorySize, SMEM1);
    cudaFuncSetAttribute((const void*)k_conv3d_mma<C2, C3, 2, 1, false>,
                         cudaFuncAttributeMaxDynamicSharedMemorySize, SMEM2);

    // weight prep (bf16 hi/lo images)
    k_wprep<CF, C2, PK1><<<(27 * C2 * CF + 255) / 256, 256>>>(w_fusion, p_wB1);
    k_wprep<C2, C3, PK2><<<(27 * C3 * C2 + 255) / 256, 256>>>(w_reg1,   p_wB2);

    // feature extraction (all 4 cams in one launch)
    k_feat4<<<dim3(FW / 16, FH / 16, 4), dim3(16, 16)>>>(cams[0], cams[1], cams[2], cams[3], w_feat);

    // plane sweep warp (warp-cooperative gather)
    k_warp<<<dim3(FH * FW / 32, DSLICE, CAMS), 256>>>(grids);

    // antialiased resize -> bf16 hi/lo cost volume (warp-cooperative)
    k_resize<<<dim3(HO * WO / 32, DSLICE, CAMS), 256>>>();

    // 3D conv stack (pipelined mma.sync bf16 split; M64xN32 / M32xN32 warp tiles)
    k_conv3d_mma<CF, C2, 4, 2, true ><<<dim3(WO / 128, HO, DSLICE), 128, SMEM1>>>(p_ch,  p_cl,  p_wB1, p_x1h, p_x1l, nullptr);
    k_conv3d_mma<C2, C3, 2, 1, false><<<dim3(WO / 128, HO, DSLICE), 128, SMEM2>>>(p_x1h, p_x1l, p_wB2, nullptr, nullptr, p_x2);

    // squeeze conv (smem-tiled)
    k_reg2<<<dim3(WO / 32, HO / 8, DSLICE), 256>>>(w_reg2);

    // disparity regression
    k_final<<<(HO * WO) / 256, 256>>>(out);
}